// round 11
// baseline (speedup 1.0000x reference)
#include <cuda_runtime.h>
#include <math.h>

typedef unsigned long long ull;

// ---------------------------------------------------------------------------
// constants
// ---------------------------------------------------------------------------
#define NSEL 4507
#define NPAD 8192
#define MW   71
#define BBOX_CLIP 4.135166556742356f
#define KU_NEGINF 0x007FFFFFu
// midpoint(0.7f, nextafterf(0.7f)): RN(inter/denom) > 0.7f  <=>  inter/denom >= IOU_MID
#define IOU_MID 0.70000001788139343262

__constant__ int   c_G[5]       = {200, 100, 50, 25, 13};
__constant__ int   c_stride[5]  = {4, 8, 16, 32, 61};
__constant__ int   c_topk[5]    = {1000, 1000, 1000, 1000, 507};
__constant__ int   c_slotoff[5] = {0, 1000, 2000, 3000, 4000};
__constant__ float c_cell[5][3][4] = {
  { {-23.f,-11.f,23.f,11.f},    {-16.f,-16.f,16.f,16.f},    {-11.f,-23.f,11.f,23.f} },
  { {-45.f,-23.f,45.f,23.f},    {-32.f,-32.f,32.f,32.f},    {-23.f,-45.f,23.f,45.f} },
  { {-91.f,-45.f,91.f,45.f},    {-64.f,-64.f,64.f,64.f},    {-45.f,-91.f,45.f,91.f} },
  { {-181.f,-91.f,181.f,91.f},  {-128.f,-128.f,128.f,128.f},{-91.f,-181.f,91.f,181.f} },
  { {-362.f,-181.f,362.f,181.f},{-256.f,-256.f,256.f,256.f},{-181.f,-362.f,181.f,362.f} },
};
__constant__ int    c_featW[4]     = {200, 100, 50, 25};
__constant__ float  c_featScale[4] = {0.25f, 0.125f, 0.0625f, 0.03125f};
__constant__ long long c_featOff[4] = {0, 20480000, 25600000, 26880000};
// stage1 transpose tiling: per level tilesP = ceil(P/32), blocks = tilesP*8*2
__constant__ int c_P[4]       = {40000, 10000, 2500, 625};
__constant__ int c_tilesP[4]  = {1250, 313, 79, 20};
__constant__ int c_lvlBlk[4]  = {20000, 5008, 1264, 320};
__constant__ int c_lvlOff4[4] = {0, 20000, 25008, 26272};
#define TRANSPOSE_BLOCKS 26592
#define STAGE1_BLOCKS (TRANSPOSE_BLOCKS + 10)

// ---------------------------------------------------------------------------
// device scratch
// ---------------------------------------------------------------------------
__device__ float  g_featT[27200000];
__device__ float4 g_boxes[2 * NSEL];
__device__ float  g_key[2 * NSEL];
__device__ int    g_maxc_bits[2];
__device__ ull    g_sk[2 * NPAD];
__device__ float4 g_sraw[2 * NSEL];
__device__ float4 g_soff[2 * NSEL];
__device__ ull    g_live[2][MW];
__device__ ull    g_mask[(size_t)2 * NSEL * MW];
__device__ int    g_lvl[2000];

struct Stage1Args {
  const float* obj[5];
  const float* dlt[5];
  const float* feat[4];
};

__device__ __forceinline__ unsigned ordkey(float v) {
  unsigned u = __float_as_uint(v);
  return (u & 0x80000000u) ? ~u : (u | 0x80000000u);
}
// exact inverse of ordkey (bijection on bit patterns)
__device__ __forceinline__ float inv_ordkey(unsigned u) {
  return (u & 0x80000000u) ? __uint_as_float(u & 0x7FFFFFFFu)
                           : __uint_as_float(~u);
}

// ---------------------------------------------------------------------------
// XLA-GPU f32 sigmoid emulation (logistic -> 0.5*tanh(0.5x)+0.5, Eigen tanh)
// ---------------------------------------------------------------------------
__device__ __forceinline__ float xla_tanh_f32(float x) {
  float ax = fabsf(x);
  float xc = fminf(fmaxf(x, -7.99881172180175781f), 7.99881172180175781f);
  float x2 = __fmul_rn(xc, xc);
  float p = __fmaf_rn(x2, -2.76076847742355e-16f, 2.00018790482477e-13f);
  p = __fmaf_rn(x2, p, -8.60467152213735e-11f);
  p = __fmaf_rn(x2, p, 5.12229709037114e-08f);
  p = __fmaf_rn(x2, p, 1.48572235717979e-05f);
  p = __fmaf_rn(x2, p, 6.37261928875436e-04f);
  p = __fmaf_rn(x2, p, 4.89352455891786e-03f);
  p = __fmul_rn(xc, p);
  float q = __fmaf_rn(x2, 1.19825839466702e-06f, 1.18534705686654e-04f);
  q = __fmaf_rn(x2, q, 2.26843463243900e-03f);
  q = __fmaf_rn(x2, q, 4.89352518554385e-03f);
  float r = __fdiv_rn(p, q);
  return (ax < 0.0004f) ? x : r;
}
__device__ __forceinline__ float xla_sigmoid(float x) {
  float t = xla_tanh_f32(__fmul_rn(0.5f, x));
  return __fadd_rn(__fmul_rn(0.5f, t), 0.5f);
}

// ---------------------------------------------------------------------------
// init
// ---------------------------------------------------------------------------
__global__ void init_kernel() {
  int t = threadIdx.x;
  if (t < 2) g_maxc_bits[t] = 0;
  if (t < 2 * MW) ((ull*)g_live)[t] = 0ull;
}

// ---------------------------------------------------------------------------
// stage1: blocks 0..9 = per-(level,image) topk + fused decode
//         blocks 10..  = feature transpose tiles (32x32)
// ---------------------------------------------------------------------------
__device__ void topk_decode_body(const Stage1Args& a, int lvl, int b) {
  int G = c_G[lvl];
  int ncell = G * G;
  int n = 3 * ncell;
  int k = c_topk[lvl];
  const float* obj = a.obj[lvl] + (size_t)b * n;

  __shared__ int hist[256];
  __shared__ unsigned sh_prefix;
  __shared__ int sh_kc;
  __shared__ int sh_cnt;
  __shared__ ull keys[1024];

  bool vec = ((n & 3) == 0);
  int nvec = n >> 2;
  int nvec_r = (nvec + 1023) & ~1023;
  int lane = threadIdx.x & 31;

  unsigned prefix = 0;
  int kc = k;
  for (int pass = 0; pass < 4; pass++) {
    int pos = 24 - 8 * pass;
    unsigned himask = (pass == 0) ? 0u : (0xFFFFFFFFu << (pos + 8));
    for (int h = threadIdx.x; h < 256; h += 1024) hist[h] = 0;
    __syncthreads();
    if (vec) {
      const float4* o4 = (const float4*)obj;
      for (int t = threadIdx.x; t < nvec_r; t += 1024) {
        bool inb = (t < nvec);
        float4 v = inb ? o4[t] : make_float4(0.f, 0.f, 0.f, 0.f);
        float vals[4] = {v.x, v.y, v.z, v.w};
#pragma unroll
        for (int e = 0; e < 4; e++) {
          unsigned u = ordkey(vals[e]);
          bool okk = inb && ((u & himask) == prefix);
          unsigned key = okk ? ((u >> pos) & 255u) : 0xFFFFFFFFu;
          unsigned mm = __match_any_sync(0xFFFFFFFFu, key);
          int leader = __ffs(mm) - 1;
          if (okk && lane == leader)
            atomicAdd(&hist[key], __popc(mm));
        }
      }
    } else {
      for (int t = threadIdx.x; t < n; t += 1024) {
        unsigned u = ordkey(obj[t]);
        if ((u & himask) == prefix) atomicAdd(&hist[(u >> pos) & 255], 1);
      }
    }
    __syncthreads();
    if (threadIdx.x == 0) {
      int cum = 0, bin = 255;
      for (; bin >= 0; bin--) {
        int c = hist[bin];
        if (cum + c >= kc) break;
        cum += c;
      }
      sh_prefix = prefix | ((unsigned)bin << pos);
      sh_kc = kc - cum;
    }
    __syncthreads();
    prefix = sh_prefix;
    kc = sh_kc;
    __syncthreads();
  }
  unsigned T = prefix;

  for (int t = threadIdx.x; t < 1024; t += 1024) keys[t] = 0ull;
  if (threadIdx.x == 0) sh_cnt = 0;
  __syncthreads();
  if (vec) {
    const float4* o4 = (const float4*)obj;
    for (int t = threadIdx.x; t < nvec; t += 1024) {
      float4 v = o4[t];
      float vals[4] = {v.x, v.y, v.z, v.w};
#pragma unroll
      for (int e = 0; e < 4; e++) {
        unsigned u = ordkey(vals[e]);
        if (u >= T) {
          int src = t * 4 + e;
          int aa = src / ncell, yx = src - aa * ncell;
          int p = atomicAdd(&sh_cnt, 1);
          if (p < 1024)
            keys[p] = ((ull)u << 32) | (unsigned)(~(yx * 3 + aa));
        }
      }
    }
  } else {
    for (int t = threadIdx.x; t < n; t += 1024) {
      unsigned u = ordkey(obj[t]);
      if (u >= T) {
        int aa = t / ncell, yx = t - aa * ncell;
        int p = atomicAdd(&sh_cnt, 1);
        if (p < 1024)
          keys[p] = ((ull)u << 32) | (unsigned)(~(yx * 3 + aa));
      }
    }
  }
  __syncthreads();
  for (int kk = 2; kk <= 1024; kk <<= 1) {
    for (int j = kk >> 1; j > 0; j >>= 1) {
      for (int t = threadIdx.x; t < 1024; t += 1024) {
        int ixj = t ^ j;
        if (ixj > t) {
          ull A = keys[t], C = keys[ixj];
          bool desc = ((t & kk) == 0);
          if (desc ? (A < C) : (A > C)) { keys[t] = C; keys[ixj] = A; }
        }
      }
      __syncthreads();
    }
  }

  // fused decode: slot = c_slotoff[lvl] + i, i < k (= lax.top_k order)
  int slotbase = b * NSEL + c_slotoff[lvl];
  const float* dl = a.dlt[lvl];
  size_t GG = (size_t)G * G;
  float st = (float)c_stride[lvl];
  for (int i = threadIdx.x; i < k; i += 1024) {
    ull K = keys[i];
    unsigned u = (unsigned)(K >> 32);
    int flat = (int)~(unsigned)(K & 0xFFFFFFFFull);
    float logit = inv_ordkey(u);
    int aa = flat % 3;
    int cell = flat / 3;
    int y = cell / G, x = cell - y * G;
    float sx = (float)x * st, sy = (float)y * st;
    float x1a = sx + c_cell[lvl][aa][0];
    float y1a = sy + c_cell[lvl][aa][1];
    float x2a = sx + c_cell[lvl][aa][2];
    float y2a = sy + c_cell[lvl][aa][3];
    float wa = x2a - x1a, ha = y2a - y1a;
    float cxa = x1a + 0.5f * wa, cya = y1a + 0.5f * ha;

    size_t p0 = ((size_t)b * 12 + aa * 4) * GG + (size_t)y * G + x;
    float dx = dl[p0], dy = dl[p0 + GG];
    float dw = fminf(dl[p0 + 2 * GG], BBOX_CLIP);
    float dh = fminf(dl[p0 + 3 * GG], BBOX_CLIP);

    float cx = __fadd_rn(__fmul_rn(dx, wa), cxa);
    float cy = __fadd_rn(__fmul_rn(dy, ha), cya);
    float w  = __fmul_rn(expf(dw), wa);
    float h  = __fmul_rn(expf(dh), ha);
    float hw = __fmul_rn(0.5f, w), hh = __fmul_rn(0.5f, h);
    float x1 = __fsub_rn(cx, hw), y1 = __fsub_rn(cy, hh);
    float x2 = __fadd_rn(cx, hw), y2 = __fadd_rn(cy, hh);
    x1 = fminf(fmaxf(x1, 0.f), 800.f);
    x2 = fminf(fmaxf(x2, 0.f), 800.f);
    y1 = fminf(fmaxf(y1, 0.f), 800.f);
    y2 = fminf(fmaxf(y2, 0.f), 800.f);
    bool valid = (__fsub_rn(x2, x1) >= 0.001f) && (__fsub_rn(y2, y1) >= 0.001f);

    g_boxes[slotbase + i] = make_float4(x1, y1, x2, y2);
    g_key[slotbase + i] = valid ? xla_sigmoid(logit) : -INFINITY;
    float m = fmaxf(fmaxf(x1, y1), fmaxf(x2, y2));
    atomicMax(&g_maxc_bits[b], __float_as_int(m));
  }
}

__device__ void transpose_body(const Stage1Args& a, int q) {
  int li = 3;
  if (q < c_lvlOff4[1]) li = 0;
  else if (q < c_lvlOff4[2]) li = 1;
  else if (q < c_lvlOff4[3]) li = 2;
  int P = c_P[li];
  int within = q - c_lvlOff4[li];
  int perB = c_tilesP[li] * 8;
  int b = within / perB;
  int r = within - b * perB;
  int p0 = (r >> 3) * 32;
  int c0 = (r & 7) * 32;
  int tx = threadIdx.x & 31, ty = threadIdx.x >> 5;

  __shared__ float tile[32][33];
  const float* in = a.feat[li];
  int p = p0 + tx, c = c0 + ty;
  if (p < P) tile[ty][tx] = in[((size_t)b * 256 + c) * P + p];
  __syncthreads();
  p = p0 + ty; c = c0 + tx;
  if (p < P)
    (g_featT + c_featOff[li] + (size_t)b * P * 256)[(size_t)p * 256 + c] = tile[tx][ty];
}

__global__ void __launch_bounds__(1024) stage1_kernel(Stage1Args a) {
  int bid = blockIdx.x;
  if (bid < 10) { topk_decode_body(a, bid >> 1, bid & 1); return; }
  transpose_body(a, bid - 10);
}

// ---------------------------------------------------------------------------
// sortA: 4 blocks; block (b, half) fully sorts its 4096 keys
// half0 descending, half1 ascending  -> concatenation is bitonic
// ---------------------------------------------------------------------------
__global__ void __launch_bounds__(1024) sortA_kernel() {
  __shared__ ull sk[4096];
  int b = blockIdx.x >> 1, half = blockIdx.x & 1;
  int base = half * 4096;
  for (int t = threadIdx.x; t < 4096; t += 1024) {
    int s = base + t;
    unsigned u = (s < NSEL) ? ordkey(g_key[b * NSEL + s]) : KU_NEGINF;
    sk[t] = ((ull)u << 32) | (unsigned)(~s);
  }
  __syncthreads();
  bool wantDesc = (half == 0);
  for (int kk = 2; kk <= 4096; kk <<= 1) {
    for (int j = kk >> 1; j > 0; j >>= 1) {
      for (int t = threadIdx.x; t < 4096; t += 1024) {
        int ixj = t ^ j;
        if (ixj > t) {
          ull A = sk[t], C = sk[ixj];
          bool descPair = (((t & kk) == 0) == wantDesc);
          if (descPair ? (A < C) : (A > C)) { sk[t] = C; sk[ixj] = A; }
        }
      }
      __syncthreads();
    }
  }
  for (int t = threadIdx.x; t < 4096; t += 1024)
    g_sk[b * NPAD + base + t] = sk[t];
}

// ---------------------------------------------------------------------------
// sortB: per-image 13-pass bitonic merge (descending) + tail
// ---------------------------------------------------------------------------
__global__ void __launch_bounds__(1024) sortB_kernel() {
  extern __shared__ ull sk[];
  int b = blockIdx.x;
  for (int t = threadIdx.x; t < NPAD; t += 1024) sk[t] = g_sk[b * NPAD + t];
  __syncthreads();
  for (int j = NPAD >> 1; j > 0; j >>= 1) {
    for (int t = threadIdx.x; t < NPAD; t += 1024) {
      int ixj = t ^ j;
      if (ixj > t) {
        ull A = sk[t], C = sk[ixj];
        if (A < C) { sk[t] = C; sk[ixj] = A; }
      }
    }
    __syncthreads();
  }
  float maxc = __int_as_float(g_maxc_bits[b]);
  float mc1 = __fadd_rn(maxc, 1.0f);
  for (int i = threadIdx.x; i < NSEL; i += 1024) {
    ull K = sk[i];
    unsigned slot = ~(unsigned)(K & 0xFFFFFFFFull);
    unsigned ku = (unsigned)(K >> 32);
    float4 bx = g_boxes[b * NSEL + slot];
    g_sraw[b * NSEL + i] = bx;
    int lvl = (slot < 1000) ? 0 : (slot < 2000) ? 1 : (slot < 3000) ? 2 : (slot < 4000) ? 3 : 4;
    float off = __fmul_rn((float)lvl, mc1);
    g_soff[b * NSEL + i] = make_float4(__fadd_rn(bx.x, off), __fadd_rn(bx.y, off),
                                       __fadd_rn(bx.z, off), __fadd_rn(bx.w, off));
    if (ku != KU_NEGINF)
      atomicOr(&g_live[b][i >> 6], 1ull << (i & 63));
  }
}

// ---------------------------------------------------------------------------
// IoU suppression bitmask (bits only for j > i); division-free exact predicate
// ---------------------------------------------------------------------------
__global__ void iou_kernel() {
  int cw = blockIdx.x, rb = blockIdx.y, b = blockIdx.z;
  int t = threadIdx.x;
  int i = rb * 64 + t;
  if (cw < rb) {
    if (i < NSEL) g_mask[((size_t)b * NSEL + i) * MW + cw] = 0ull;
    return;
  }
  __shared__ float4 cb[64];
  __shared__ float  ca[64];
  int j0 = cw * 64;
  if (j0 + t < NSEL) {
    float4 q = g_soff[b * NSEL + j0 + t];
    cb[t] = q;
    ca[t] = __fmul_rn(__fsub_rn(q.z, q.x), __fsub_rn(q.w, q.y));
  } else {
    cb[t] = make_float4(0.f, 0.f, 0.f, 0.f);
    ca[t] = 0.f;
  }
  __syncthreads();
  if (i >= NSEL) return;
  float4 p = g_soff[b * NSEL + i];
  float pa = __fmul_rn(__fsub_rn(p.z, p.x), __fsub_rn(p.w, p.y));
  ull bits = 0;
#pragma unroll 4
  for (int jj = 0; jj < 64; jj++) {
    int j = j0 + jj;
    if (j > i && j < NSEL) {
      float4 q = cb[jj];
      float ltx = fmaxf(p.x, q.x), lty = fmaxf(p.y, q.y);
      float rbx = fminf(p.z, q.z), rby = fminf(p.w, q.w);
      float w = fmaxf(__fsub_rn(rbx, ltx), 0.f);
      float h = fmaxf(__fsub_rn(rby, lty), 0.f);
      float inter = __fmul_rn(w, h);
      if (inter > 0.f) {
        float denom = __fsub_rn(__fadd_rn(pa, ca[jj]), inter);
        if ((double)inter >= IOU_MID * (double)denom)
          bits |= 1ull << jj;
      }
    }
  }
  g_mask[((size_t)b * NSEL + i) * MW + cw] = bits;
}

// ---------------------------------------------------------------------------
// sequential NMS scan (1 warp / image) + final boxes + fused lvl assignment
// ---------------------------------------------------------------------------
__device__ __forceinline__ void cpasync8(void* sm, const void* gm) {
  unsigned sa = (unsigned)__cvta_generic_to_shared(sm);
  asm volatile("cp.async.ca.shared.global [%0], [%1], 8;" :: "r"(sa), "l"(gm));
}

__global__ void nms_scan_kernel(float* __restrict__ fin) {
  int b = blockIdx.x;
  int lane = threadIdx.x;
  __shared__ ull ring[16][MW];
  __shared__ int keep_s[1000];

  int w0 = lane, w1 = 32 + lane, w2 = 64 + lane;
  ull live0 = (w0 < MW) ? g_live[b][w0] : 0ull;
  ull live1 = (w1 < MW) ? g_live[b][w1] : 0ull;
  ull live2 = (w2 < MW) ? g_live[b][w2] : 0ull;
  ull remv0 = 0, remv1 = 0, remv2 = 0;

  const ull* mbase = g_mask + (size_t)b * NSEL * MW;
  for (int d = 0; d < 16; d++) {
    if (w0 < MW) cpasync8(&ring[d][w0], &mbase[(size_t)d * MW + w0]);
    if (w1 < MW) cpasync8(&ring[d][w1], &mbase[(size_t)d * MW + w1]);
    if (w2 < MW) cpasync8(&ring[d][w2], &mbase[(size_t)d * MW + w2]);
    asm volatile("cp.async.commit_group;");
  }

  ull cur = 0;
  int cnt = 0;
  for (int i = 0; i < NSEL; i++) {
    asm volatile("cp.async.wait_group 15;");
    int iw = i >> 6, ib = i & 63;
    if (ib == 0) {
      int s = iw >> 5;
      ull lv = (s == 0) ? live0 : ((s == 1) ? live1 : live2);
      ull rv = (s == 0) ? remv0 : ((s == 1) ? remv1 : remv2);
      cur = __shfl_sync(0xFFFFFFFFu, lv & ~rv, iw & 31);
    }
    if ((cur >> ib) & 1ull) {
      int slot = i & 15;
      if (w0 < MW) remv0 |= ring[slot][w0];
      if (w1 < MW) remv1 |= ring[slot][w1];
      if (w2 < MW) remv2 |= ring[slot][w2];
      cur &= ~ring[slot][iw];
      if (lane == 0) keep_s[cnt] = i;
      cnt++;
      if (cnt >= 1000) break;
    }
    int pf = i + 16;
    if (pf < NSEL) {
      int slot = pf & 15;
      if (w0 < MW) cpasync8(&ring[slot][w0], &mbase[(size_t)pf * MW + w0]);
      if (w1 < MW) cpasync8(&ring[slot][w1], &mbase[(size_t)pf * MW + w1]);
      if (w2 < MW) cpasync8(&ring[slot][w2], &mbase[(size_t)pf * MW + w2]);
    }
    asm volatile("cp.async.commit_group;");
  }
  asm volatile("cp.async.wait_all;");
  __syncwarp();
  float4* fo = (float4*)fin;
  for (int j = lane; j < 1000; j += 32) {
    float4 v = make_float4(0.f, 0.f, 0.f, 0.f);
    if (j < cnt) v = g_sraw[b * NSEL + keep_s[j]];
    fo[b * 1000 + j] = v;
    // fused roi level assignment (zero boxes -> lvl 0, same as reference)
    float area = __fmul_rn(__fsub_rn(v.z, v.x), __fsub_rn(v.w, v.y));
    float arg = __fadd_rn(__fdiv_rn(sqrtf(area), 224.0f), 1e-6f);
    float l = floorf(__fadd_rn(4.0f, log2f(arg)));
    l = fminf(fmaxf(l, 2.0f), 5.0f);
    g_lvl[b * 1000 + j] = (int)l - 2;
  }
}

// ---------------------------------------------------------------------------
// roi align: 1 block per roi, 256 channel threads
// ---------------------------------------------------------------------------
__global__ void __launch_bounds__(256) roialign_kernel(const float* __restrict__ fin,
                                                       float* __restrict__ out) {
  extern __shared__ float outs[];  // [49][257]
  __shared__ float lx[14], hx[14], ly[14], hy[14], vxf[14], vyf[14];
  __shared__ int xl[14], xh[14], yl[14], yh[14];

  int r = blockIdx.x;
  int c = threadIdx.x;
  int li = g_lvl[r];
  float4 roi = ((const float4*)fin)[r];
  int W = c_featW[li];
  float sc = c_featScale[li];
  int b = r / 1000;

  if (c < 14) {
    float x1 = __fmul_rn(roi.x, sc), x2 = __fmul_rn(roi.z, sc);
    float bw = __fdiv_rn(fmaxf(__fsub_rn(x2, x1), 1.0f), 7.0f);
    float gg = ((float)c + 0.5f) / 2.0f;
    float xs = __fadd_rn(x1, __fmul_rn(bw, gg));
    vxf[c] = (xs >= -1.0f && xs <= (float)W) ? 1.0f : 0.0f;
    float xc = fminf(fmaxf(xs, 0.0f), (float)(W - 1));
    int xlo = (int)floorf(xc);
    xl[c] = xlo;
    xh[c] = min(xlo + 1, W - 1);
    float l = __fsub_rn(xc, (float)xlo);
    lx[c] = l;
    hx[c] = 1.0f - l;
  }
  if (c >= 16 && c < 30) {
    int q = c - 16;
    float y1 = __fmul_rn(roi.y, sc), y2 = __fmul_rn(roi.w, sc);
    float bh = __fdiv_rn(fmaxf(__fsub_rn(y2, y1), 1.0f), 7.0f);
    float gg = ((float)q + 0.5f) / 2.0f;
    float ys = __fadd_rn(y1, __fmul_rn(bh, gg));
    vyf[q] = (ys >= -1.0f && ys <= (float)W) ? 1.0f : 0.0f;
    float yc = fminf(fmaxf(ys, 0.0f), (float)(W - 1));
    int ylo = (int)floorf(yc);
    yl[q] = ylo;
    yh[q] = min(ylo + 1, W - 1);
    float l = __fsub_rn(yc, (float)ylo);
    ly[q] = l;
    hy[q] = 1.0f - l;
  }
  __syncthreads();

  const float* F = g_featT + c_featOff[li] + (size_t)b * W * W * 256 + c;
#pragma unroll 1
  for (int p = 0; p < 49; p++) {
    int py = p / 7, px = p - py * 7;
    float acc = 0.f;
#pragma unroll
    for (int sy = 0; sy < 2; sy++) {
#pragma unroll
      for (int sxi = 0; sxi < 2; sxi++) {
        int ii = py * 2 + sy, jj = px * 2 + sxi;
        int y0 = yl[ii], y1 = yh[ii], x0 = xl[jj], x1 = xh[jj];
        const float* r0 = F + (size_t)(y0 * W) * 256;
        const float* r1 = F + (size_t)(y1 * W) * 256;
        float v00 = r0[(size_t)x0 * 256];
        float v01 = r0[(size_t)x1 * 256];
        float v10 = r1[(size_t)x0 * 256];
        float v11 = r1[(size_t)x1 * 256];
        float t = (hy[ii] * hx[jj]) * v00 + (hy[ii] * lx[jj]) * v01 +
                  (ly[ii] * hx[jj]) * v10 + (ly[ii] * lx[jj]) * v11;
        acc += t * (vyf[ii] * vxf[jj]);
      }
    }
    outs[p * 257 + c] = acc * 0.25f;
  }
  __syncthreads();
  float* o = out + (size_t)r * 12544;
  for (int g = c; g < 12544; g += 256) {
    int cc = g / 49, pp = g - cc * 49;
    o[g] = outs[pp * 257 + cc];
  }
}

// ---------------------------------------------------------------------------
// launch
// ---------------------------------------------------------------------------
extern "C" void kernel_launch(void* const* d_in, const int* in_sizes, int n_in,
                              void* d_out, int out_size) {
  (void)n_in; (void)out_size;
  Stage1Args a;
  bool interleaved = (in_sizes[2] == 4 * in_sizes[1]);
  for (int i = 0; i < 5; i++) {
    if (interleaved) {
      a.obj[i] = (const float*)d_in[1 + 2 * i];
      a.dlt[i] = (const float*)d_in[2 + 2 * i];
    } else {
      a.obj[i] = (const float*)d_in[1 + i];
      a.dlt[i] = (const float*)d_in[6 + i];
    }
  }
  for (int i = 0; i < 4; i++) a.feat[i] = (const float*)d_in[11 + i];
  float* fin = (float*)d_out;
  float* bf  = (float*)d_out + 8000;

  cudaFuncSetAttribute(sortB_kernel, cudaFuncAttributeMaxDynamicSharedMemorySize, 65536);
  cudaFuncSetAttribute(roialign_kernel, cudaFuncAttributeMaxDynamicSharedMemorySize, 50372);

  init_kernel<<<1, 256>>>();
  stage1_kernel<<<STAGE1_BLOCKS, 1024>>>(a);
  sortA_kernel<<<4, 1024>>>();
  sortB_kernel<<<2, 1024, 65536>>>();
  iou_kernel<<<dim3(MW, MW, 2), 64>>>();
  nms_scan_kernel<<<2, 32>>>(fin);
  roialign_kernel<<<2000, 256, 50372>>>(fin, bf);
}

// round 12
// speedup vs baseline: 1.0759x; 1.0759x over previous
#include <cuda_runtime.h>
#include <math.h>

typedef unsigned long long ull;

// ---------------------------------------------------------------------------
// constants
// ---------------------------------------------------------------------------
#define NSEL 4507
#define NPAD 8192
#define MW   71
#define MWP  72   // padded mask row (576B, 16B-aligned); word 71 always zero
#define BBOX_CLIP 4.135166556742356f
#define KU_NEGINF 0x007FFFFFu
// midpoint(0.7f, nextafterf(0.7f)): RN(inter/denom) > 0.7f  <=>  inter/denom >= IOU_MID
#define IOU_MID 0.70000001788139343262

__constant__ int   c_G[5]       = {200, 100, 50, 25, 13};
__constant__ int   c_stride[5]  = {4, 8, 16, 32, 61};
__constant__ int   c_topk[5]    = {1000, 1000, 1000, 1000, 507};
__constant__ int   c_slotoff[5] = {0, 1000, 2000, 3000, 4000};
__constant__ float c_cell[5][3][4] = {
  { {-23.f,-11.f,23.f,11.f},    {-16.f,-16.f,16.f,16.f},    {-11.f,-23.f,11.f,23.f} },
  { {-45.f,-23.f,45.f,23.f},    {-32.f,-32.f,32.f,32.f},    {-23.f,-45.f,23.f,45.f} },
  { {-91.f,-45.f,91.f,45.f},    {-64.f,-64.f,64.f,64.f},    {-45.f,-91.f,45.f,91.f} },
  { {-181.f,-91.f,181.f,91.f},  {-128.f,-128.f,128.f,128.f},{-91.f,-181.f,91.f,181.f} },
  { {-362.f,-181.f,362.f,181.f},{-256.f,-256.f,256.f,256.f},{-181.f,-362.f,181.f,362.f} },
};
__constant__ int    c_featW[4]     = {200, 100, 50, 25};
__constant__ float  c_featScale[4] = {0.25f, 0.125f, 0.0625f, 0.03125f};
__constant__ long long c_featOff[4] = {0, 20480000, 25600000, 26880000};

// ---------------------------------------------------------------------------
// device scratch
// ---------------------------------------------------------------------------
__device__ float  g_featT[27200000];
__device__ float4 g_boxes[2 * NSEL];
__device__ float  g_key[2 * NSEL];
__device__ int    g_maxc_bits[2];
__device__ ull    g_sk[2 * NPAD];
__device__ float4 g_sraw[2 * NSEL];
__device__ float4 g_soff[2 * NSEL];
__device__ ull    g_live[2][MW];
__device__ __align__(16) ull g_mask[(size_t)2 * NSEL * MWP];
__device__ int    g_lvl[2000];

struct InPtrs {
  const float* obj[5];
  const float* dlt[5];
};

__device__ __forceinline__ unsigned ordkey(float v) {
  unsigned u = __float_as_uint(v);
  return (u & 0x80000000u) ? ~u : (u | 0x80000000u);
}
__device__ __forceinline__ float inv_ordkey(unsigned u) {
  return (u & 0x80000000u) ? __uint_as_float(u & 0x7FFFFFFFu)
                           : __uint_as_float(~u);
}

// ---------------------------------------------------------------------------
// XLA-GPU f32 sigmoid emulation (logistic -> 0.5*tanh(0.5x)+0.5, Eigen tanh)
// ---------------------------------------------------------------------------
__device__ __forceinline__ float xla_tanh_f32(float x) {
  float ax = fabsf(x);
  float xc = fminf(fmaxf(x, -7.99881172180175781f), 7.99881172180175781f);
  float x2 = __fmul_rn(xc, xc);
  float p = __fmaf_rn(x2, -2.76076847742355e-16f, 2.00018790482477e-13f);
  p = __fmaf_rn(x2, p, -8.60467152213735e-11f);
  p = __fmaf_rn(x2, p, 5.12229709037114e-08f);
  p = __fmaf_rn(x2, p, 1.48572235717979e-05f);
  p = __fmaf_rn(x2, p, 6.37261928875436e-04f);
  p = __fmaf_rn(x2, p, 4.89352455891786e-03f);
  p = __fmul_rn(xc, p);
  float q = __fmaf_rn(x2, 1.19825839466702e-06f, 1.18534705686654e-04f);
  q = __fmaf_rn(x2, q, 2.26843463243900e-03f);
  q = __fmaf_rn(x2, q, 4.89352518554385e-03f);
  float r = __fdiv_rn(p, q);
  return (ax < 0.0004f) ? x : r;
}
__device__ __forceinline__ float xla_sigmoid(float x) {
  float t = xla_tanh_f32(__fmul_rn(0.5f, x));
  return __fadd_rn(__fmul_rn(0.5f, t), 0.5f);
}

// ---------------------------------------------------------------------------
// init
// ---------------------------------------------------------------------------
__global__ void init_kernel() {
  int t = threadIdx.x;
  if (t < 2) g_maxc_bits[t] = 0;
  if (t < 2 * MW) ((ull*)g_live)[t] = 0ull;
}

// ---------------------------------------------------------------------------
// transpose feats (B,256,P) -> (B,P,256)  [round-10 proven version]
// ---------------------------------------------------------------------------
__global__ void transpose_kernel(const float* __restrict__ in, int P, long long outOff) {
  __shared__ float tile[32][33];
  int b = blockIdx.z;
  int p0 = blockIdx.x * 32, c0 = blockIdx.y * 32;
  int tx = threadIdx.x, ty = threadIdx.y;
#pragma unroll
  for (int rr = 0; rr < 4; rr++) {
    int c = c0 + ty + rr * 8;
    int p = p0 + tx;
    if (p < P) tile[ty + rr * 8][tx] = in[((size_t)b * 256 + c) * P + p];
  }
  __syncthreads();
  float* out = g_featT + outOff + (size_t)b * P * 256;
#pragma unroll
  for (int rr = 0; rr < 4; rr++) {
    int p = p0 + ty + rr * 8;
    int c = c0 + tx;
    if (p < P) out[(size_t)p * 256 + c] = tile[tx][ty + rr * 8];
  }
}

// ---------------------------------------------------------------------------
// exact top-k per (level, image) + fused decode
// ---------------------------------------------------------------------------
__global__ void __launch_bounds__(1024) topk_kernel(InPtrs a) {
  int lvl = blockIdx.x, b = blockIdx.y;
  int G = c_G[lvl];
  int ncell = G * G;
  int n = 3 * ncell;
  int k = c_topk[lvl];
  const float* obj = a.obj[lvl] + (size_t)b * n;

  __shared__ int hist[256];
  __shared__ unsigned sh_prefix;
  __shared__ int sh_kc;
  __shared__ int sh_cnt;
  __shared__ ull keys[1024];

  bool vec = ((n & 3) == 0);
  int nvec = n >> 2;
  int nvec_r = (nvec + 1023) & ~1023;
  int lane = threadIdx.x & 31;

  unsigned prefix = 0;
  int kc = k;
  for (int pass = 0; pass < 4; pass++) {
    int pos = 24 - 8 * pass;
    unsigned himask = (pass == 0) ? 0u : (0xFFFFFFFFu << (pos + 8));
    for (int h = threadIdx.x; h < 256; h += 1024) hist[h] = 0;
    __syncthreads();
    if (vec) {
      const float4* o4 = (const float4*)obj;
      for (int t = threadIdx.x; t < nvec_r; t += 1024) {
        bool inb = (t < nvec);
        float4 v = inb ? o4[t] : make_float4(0.f, 0.f, 0.f, 0.f);
        float vals[4] = {v.x, v.y, v.z, v.w};
#pragma unroll
        for (int e = 0; e < 4; e++) {
          unsigned u = ordkey(vals[e]);
          bool okk = inb && ((u & himask) == prefix);
          unsigned key = okk ? ((u >> pos) & 255u) : 0xFFFFFFFFu;
          unsigned mm = __match_any_sync(0xFFFFFFFFu, key);
          int leader = __ffs(mm) - 1;
          if (okk && lane == leader)
            atomicAdd(&hist[key], __popc(mm));
        }
      }
    } else {
      for (int t = threadIdx.x; t < n; t += 1024) {
        unsigned u = ordkey(obj[t]);
        if ((u & himask) == prefix) atomicAdd(&hist[(u >> pos) & 255], 1);
      }
    }
    __syncthreads();
    if (threadIdx.x == 0) {
      int cum = 0, bin = 255;
      for (; bin >= 0; bin--) {
        int c = hist[bin];
        if (cum + c >= kc) break;
        cum += c;
      }
      sh_prefix = prefix | ((unsigned)bin << pos);
      sh_kc = kc - cum;
    }
    __syncthreads();
    prefix = sh_prefix;
    kc = sh_kc;
    __syncthreads();
  }
  unsigned T = prefix;

  for (int t = threadIdx.x; t < 1024; t += 1024) keys[t] = 0ull;
  if (threadIdx.x == 0) sh_cnt = 0;
  __syncthreads();
  if (vec) {
    const float4* o4 = (const float4*)obj;
    for (int t = threadIdx.x; t < nvec; t += 1024) {
      float4 v = o4[t];
      float vals[4] = {v.x, v.y, v.z, v.w};
#pragma unroll
      for (int e = 0; e < 4; e++) {
        unsigned u = ordkey(vals[e]);
        if (u >= T) {
          int src = t * 4 + e;
          int aa = src / ncell, yx = src - aa * ncell;
          int p = atomicAdd(&sh_cnt, 1);
          if (p < 1024)
            keys[p] = ((ull)u << 32) | (unsigned)(~(yx * 3 + aa));
        }
      }
    }
  } else {
    for (int t = threadIdx.x; t < n; t += 1024) {
      unsigned u = ordkey(obj[t]);
      if (u >= T) {
        int aa = t / ncell, yx = t - aa * ncell;
        int p = atomicAdd(&sh_cnt, 1);
        if (p < 1024)
          keys[p] = ((ull)u << 32) | (unsigned)(~(yx * 3 + aa));
      }
    }
  }
  __syncthreads();
  for (int kk = 2; kk <= 1024; kk <<= 1) {
    for (int j = kk >> 1; j > 0; j >>= 1) {
      for (int t = threadIdx.x; t < 1024; t += 1024) {
        int ixj = t ^ j;
        if (ixj > t) {
          ull A = keys[t], C = keys[ixj];
          bool desc = ((t & kk) == 0);
          if (desc ? (A < C) : (A > C)) { keys[t] = C; keys[ixj] = A; }
        }
      }
      __syncthreads();
    }
  }

  // fused decode
  int slotbase = b * NSEL + c_slotoff[lvl];
  const float* dl = a.dlt[lvl];
  size_t GG = (size_t)G * G;
  float st = (float)c_stride[lvl];
  for (int i = threadIdx.x; i < k; i += 1024) {
    ull K = keys[i];
    unsigned u = (unsigned)(K >> 32);
    int flat = (int)~(unsigned)(K & 0xFFFFFFFFull);
    float logit = inv_ordkey(u);
    int aa = flat % 3;
    int cell = flat / 3;
    int y = cell / G, x = cell - y * G;
    float sx = (float)x * st, sy = (float)y * st;
    float x1a = sx + c_cell[lvl][aa][0];
    float y1a = sy + c_cell[lvl][aa][1];
    float x2a = sx + c_cell[lvl][aa][2];
    float y2a = sy + c_cell[lvl][aa][3];
    float wa = x2a - x1a, ha = y2a - y1a;
    float cxa = x1a + 0.5f * wa, cya = y1a + 0.5f * ha;

    size_t p0 = ((size_t)b * 12 + aa * 4) * GG + (size_t)y * G + x;
    float dx = dl[p0], dy = dl[p0 + GG];
    float dw = fminf(dl[p0 + 2 * GG], BBOX_CLIP);
    float dh = fminf(dl[p0 + 3 * GG], BBOX_CLIP);

    float cx = __fadd_rn(__fmul_rn(dx, wa), cxa);
    float cy = __fadd_rn(__fmul_rn(dy, ha), cya);
    float w  = __fmul_rn(expf(dw), wa);
    float h  = __fmul_rn(expf(dh), ha);
    float hw = __fmul_rn(0.5f, w), hh = __fmul_rn(0.5f, h);
    float x1 = __fsub_rn(cx, hw), y1 = __fsub_rn(cy, hh);
    float x2 = __fadd_rn(cx, hw), y2 = __fadd_rn(cy, hh);
    x1 = fminf(fmaxf(x1, 0.f), 800.f);
    x2 = fminf(fmaxf(x2, 0.f), 800.f);
    y1 = fminf(fmaxf(y1, 0.f), 800.f);
    y2 = fminf(fmaxf(y2, 0.f), 800.f);
    bool valid = (__fsub_rn(x2, x1) >= 0.001f) && (__fsub_rn(y2, y1) >= 0.001f);

    g_boxes[slotbase + i] = make_float4(x1, y1, x2, y2);
    g_key[slotbase + i] = valid ? xla_sigmoid(logit) : -INFINITY;
    float m = fmaxf(fmaxf(x1, y1), fmaxf(x2, y2));
    atomicMax(&g_maxc_bits[b], __float_as_int(m));
  }
}

// ---------------------------------------------------------------------------
// sortA: 4 blocks; block (b, half) fully sorts its 4096 keys
// half0 descending, half1 ascending  -> concatenation is bitonic
// ---------------------------------------------------------------------------
__global__ void __launch_bounds__(1024) sortA_kernel() {
  __shared__ ull sk[4096];
  int b = blockIdx.x >> 1, half = blockIdx.x & 1;
  int base = half * 4096;
  for (int t = threadIdx.x; t < 4096; t += 1024) {
    int s = base + t;
    unsigned u = (s < NSEL) ? ordkey(g_key[b * NSEL + s]) : KU_NEGINF;
    sk[t] = ((ull)u << 32) | (unsigned)(~s);
  }
  __syncthreads();
  bool wantDesc = (half == 0);
  for (int kk = 2; kk <= 4096; kk <<= 1) {
    for (int j = kk >> 1; j > 0; j >>= 1) {
      for (int t = threadIdx.x; t < 4096; t += 1024) {
        int ixj = t ^ j;
        if (ixj > t) {
          ull A = sk[t], C = sk[ixj];
          bool descPair = (((t & kk) == 0) == wantDesc);
          if (descPair ? (A < C) : (A > C)) { sk[t] = C; sk[ixj] = A; }
        }
      }
      __syncthreads();
    }
  }
  for (int t = threadIdx.x; t < 4096; t += 1024)
    g_sk[b * NPAD + base + t] = sk[t];
}

// ---------------------------------------------------------------------------
// sortB: per-image 13-pass bitonic merge (descending) + tail
// ---------------------------------------------------------------------------
__global__ void __launch_bounds__(1024) sortB_kernel() {
  extern __shared__ ull sk[];
  int b = blockIdx.x;
  for (int t = threadIdx.x; t < NPAD; t += 1024) sk[t] = g_sk[b * NPAD + t];
  __syncthreads();
  for (int j = NPAD >> 1; j > 0; j >>= 1) {
    for (int t = threadIdx.x; t < NPAD; t += 1024) {
      int ixj = t ^ j;
      if (ixj > t) {
        ull A = sk[t], C = sk[ixj];
        if (A < C) { sk[t] = C; sk[ixj] = A; }
      }
    }
    __syncthreads();
  }
  float maxc = __int_as_float(g_maxc_bits[b]);
  float mc1 = __fadd_rn(maxc, 1.0f);
  for (int i = threadIdx.x; i < NSEL; i += 1024) {
    ull K = sk[i];
    unsigned slot = ~(unsigned)(K & 0xFFFFFFFFull);
    unsigned ku = (unsigned)(K >> 32);
    float4 bx = g_boxes[b * NSEL + slot];
    g_sraw[b * NSEL + i] = bx;
    int lvl = (slot < 1000) ? 0 : (slot < 2000) ? 1 : (slot < 3000) ? 2 : (slot < 4000) ? 3 : 4;
    float off = __fmul_rn((float)lvl, mc1);
    g_soff[b * NSEL + i] = make_float4(__fadd_rn(bx.x, off), __fadd_rn(bx.y, off),
                                       __fadd_rn(bx.z, off), __fadd_rn(bx.w, off));
    if (ku != KU_NEGINF)
      atomicOr(&g_live[b][i >> 6], 1ull << (i & 63));
  }
}

// ---------------------------------------------------------------------------
// IoU suppression bitmask. Upper triangle (cw >= rb) only; lower-tri words
// are never written and stay BSS-zero (provably never influence the scan).
// ---------------------------------------------------------------------------
__global__ void iou_kernel() {
  int cw = blockIdx.x, rb = blockIdx.y, b = blockIdx.z;
  if (cw < rb) return;
  int t = threadIdx.x;
  int i = rb * 64 + t;
  __shared__ float4 cb[64];
  __shared__ float  ca[64];
  int j0 = cw * 64;
  if (j0 + t < NSEL) {
    float4 q = g_soff[b * NSEL + j0 + t];
    cb[t] = q;
    ca[t] = __fmul_rn(__fsub_rn(q.z, q.x), __fsub_rn(q.w, q.y));
  } else {
    cb[t] = make_float4(0.f, 0.f, 0.f, 0.f);
    ca[t] = 0.f;
  }
  __syncthreads();
  if (i >= NSEL) return;
  float4 p = g_soff[b * NSEL + i];
  float pa = __fmul_rn(__fsub_rn(p.z, p.x), __fsub_rn(p.w, p.y));
  ull bits = 0;
#pragma unroll 4
  for (int jj = 0; jj < 64; jj++) {
    int j = j0 + jj;
    if (j > i && j < NSEL) {
      float4 q = cb[jj];
      float ltx = fmaxf(p.x, q.x), lty = fmaxf(p.y, q.y);
      float rbx = fminf(p.z, q.z), rby = fminf(p.w, q.w);
      float w = fmaxf(__fsub_rn(rbx, ltx), 0.f);
      float h = fmaxf(__fsub_rn(rby, lty), 0.f);
      float inter = __fmul_rn(w, h);
      if (inter > 0.f) {
        float denom = __fsub_rn(__fadd_rn(pa, ca[jj]), inter);
        if ((double)inter >= IOU_MID * (double)denom)
          bits |= 1ull << jj;
      }
    }
  }
  g_mask[((size_t)b * NSEL + i) * MWP + cw] = bits;
}

// ---------------------------------------------------------------------------
// NMS scan: word-skip over set bits; liveness-gated monotone prefetch with
// one commit-group per row (wait_group 16 => row ready). Fused lvl assign.
// ---------------------------------------------------------------------------
__device__ __forceinline__ void cpasync16(void* sm, const void* gm) {
  unsigned sa = (unsigned)__cvta_generic_to_shared(sm);
  asm volatile("cp.async.ca.shared.global [%0], [%1], 16;" :: "r"(sa), "l"(gm));
}

__global__ void nms_scan_kernel(float* __restrict__ fin) {
  int b = blockIdx.x;
  int lane = threadIdx.x;
  __shared__ __align__(16) ull ring[32][MWP];
  __shared__ int keep_s[1000];

  int w0 = lane, w1 = 32 + lane, w2 = 64 + lane;  // w2 valid for lane<8 (MWP)
  ull live0 = g_live[b][w0];
  ull live1 = g_live[b][w1];
  ull live2 = (w2 < MW) ? g_live[b][w2] : 0ull;
  ull remv0 = 0, remv1 = 0, remv2 = 0;

  const ull* mbase = g_mask + (size_t)b * NSEL * MWP;

  int pf_next = 0, pf_word = -1;
  ull pw = 0;
  int cnt = 0;
  bool done = false;

  for (int iw = 0; iw < MW && !done; iw++) {
    int s = iw >> 5;
    ull lv = (s == 0) ? live0 : ((s == 1) ? live1 : live2);
    ull rv = (s == 0) ? remv0 : ((s == 1) ? remv1 : remv2);
    ull cur = __shfl_sync(0xFFFFFFFFu, lv & ~rv, iw & 31);
    while (cur) {
      int ib = __ffsll(cur) - 1;
      int i = iw * 64 + ib;
      // advance prefetch cursor to i+16 (liveness-gated)
      int lim = i + 16; if (lim > NSEL - 1) lim = NSEL - 1;
      while (pf_next <= lim) {
        int w = pf_next >> 6;
        if (w != pf_word) {
          int ss = w >> 5;
          ull plv = (ss == 0) ? live0 : ((ss == 1) ? live1 : live2);
          ull prv = (ss == 0) ? remv0 : ((ss == 1) ? remv1 : remv2);
          pw = __shfl_sync(0xFFFFFFFFu, plv & ~prv, w & 31);
          pf_word = w;
        }
        if ((pw >> (pf_next & 63)) & 1ull) {
          const ull* mrow = mbase + (size_t)pf_next * MWP;
          ull* dst = ring[pf_next & 31];
          cpasync16(&dst[lane * 2], mrow + lane * 2);
          if (lane < 4) cpasync16(&dst[64 + lane * 2], mrow + 64 + lane * 2);
        }
        asm volatile("cp.async.commit_group;");
        pf_next++;
      }
      if (i + 16 < NSEL) asm volatile("cp.async.wait_group 16;");
      else               asm volatile("cp.async.wait_all;");
      int slot = i & 31;
      remv0 |= ring[slot][w0];
      remv1 |= ring[slot][w1];
      if (lane < 8) remv2 |= ring[slot][w2];
      cur = (cur & (cur - 1)) & ~ring[slot][iw];
      if (lane == 0) keep_s[cnt] = i;
      cnt++;
      if (cnt >= 1000) { done = true; break; }
    }
  }
  asm volatile("cp.async.wait_all;");
  __syncwarp();
  float4* fo = (float4*)fin;
  for (int j = lane; j < 1000; j += 32) {
    float4 v = make_float4(0.f, 0.f, 0.f, 0.f);
    if (j < cnt) v = g_sraw[b * NSEL + keep_s[j]];
    fo[b * 1000 + j] = v;
    float area = __fmul_rn(__fsub_rn(v.z, v.x), __fsub_rn(v.w, v.y));
    float arg = __fadd_rn(__fdiv_rn(sqrtf(area), 224.0f), 1e-6f);
    float l = floorf(__fadd_rn(4.0f, log2f(arg)));
    l = fminf(fmaxf(l, 2.0f), 5.0f);
    g_lvl[b * 1000 + j] = (int)l - 2;
  }
}

// ---------------------------------------------------------------------------
// roi align: 1 block per roi, 256 channel threads
// ---------------------------------------------------------------------------
__global__ void __launch_bounds__(256) roialign_kernel(const float* __restrict__ fin,
                                                       float* __restrict__ out) {
  extern __shared__ float outs[];  // [49][257]
  __shared__ float lx[14], hx[14], ly[14], hy[14], vxf[14], vyf[14];
  __shared__ int xl[14], xh[14], yl[14], yh[14];

  int r = blockIdx.x;
  int c = threadIdx.x;
  int li = g_lvl[r];
  float4 roi = ((const float4*)fin)[r];
  int W = c_featW[li];
  float sc = c_featScale[li];
  int b = r / 1000;

  if (c < 14) {
    float x1 = __fmul_rn(roi.x, sc), x2 = __fmul_rn(roi.z, sc);
    float bw = __fdiv_rn(fmaxf(__fsub_rn(x2, x1), 1.0f), 7.0f);
    float gg = ((float)c + 0.5f) / 2.0f;
    float xs = __fadd_rn(x1, __fmul_rn(bw, gg));
    vxf[c] = (xs >= -1.0f && xs <= (float)W) ? 1.0f : 0.0f;
    float xc = fminf(fmaxf(xs, 0.0f), (float)(W - 1));
    int xlo = (int)floorf(xc);
    xl[c] = xlo;
    xh[c] = min(xlo + 1, W - 1);
    float l = __fsub_rn(xc, (float)xlo);
    lx[c] = l;
    hx[c] = 1.0f - l;
  }
  if (c >= 16 && c < 30) {
    int q = c - 16;
    float y1 = __fmul_rn(roi.y, sc), y2 = __fmul_rn(roi.w, sc);
    float bh = __fdiv_rn(fmaxf(__fsub_rn(y2, y1), 1.0f), 7.0f);
    float gg = ((float)q + 0.5f) / 2.0f;
    float ys = __fadd_rn(y1, __fmul_rn(bh, gg));
    vyf[q] = (ys >= -1.0f && ys <= (float)W) ? 1.0f : 0.0f;
    float yc = fminf(fmaxf(ys, 0.0f), (float)(W - 1));
    int ylo = (int)floorf(yc);
    yl[q] = ylo;
    yh[q] = min(ylo + 1, W - 1);
    float l = __fsub_rn(yc, (float)ylo);
    ly[q] = l;
    hy[q] = 1.0f - l;
  }
  __syncthreads();

  const float* F = g_featT + c_featOff[li] + (size_t)b * W * W * 256 + c;
#pragma unroll 1
  for (int p = 0; p < 49; p++) {
    int py = p / 7, px = p - py * 7;
    float acc = 0.f;
#pragma unroll
    for (int sy = 0; sy < 2; sy++) {
#pragma unroll
      for (int sxi = 0; sxi < 2; sxi++) {
        int ii = py * 2 + sy, jj = px * 2 + sxi;
        int y0 = yl[ii], y1 = yh[ii], x0 = xl[jj], x1 = xh[jj];
        const float* r0 = F + (size_t)(y0 * W) * 256;
        const float* r1 = F + (size_t)(y1 * W) * 256;
        float v00 = r0[(size_t)x0 * 256];
        float v01 = r0[(size_t)x1 * 256];
        float v10 = r1[(size_t)x0 * 256];
        float v11 = r1[(size_t)x1 * 256];
        float t = (hy[ii] * hx[jj]) * v00 + (hy[ii] * lx[jj]) * v01 +
                  (ly[ii] * hx[jj]) * v10 + (ly[ii] * lx[jj]) * v11;
        acc += t * (vyf[ii] * vxf[jj]);
      }
    }
    outs[p * 257 + c] = acc * 0.25f;
  }
  __syncthreads();
  float* o = out + (size_t)r * 12544;
  for (int g = c; g < 12544; g += 256) {
    int cc = g / 49, pp = g - cc * 49;
    o[g] = outs[pp * 257 + cc];
  }
}

// ---------------------------------------------------------------------------
// launch
// ---------------------------------------------------------------------------
extern "C" void kernel_launch(void* const* d_in, const int* in_sizes, int n_in,
                              void* d_out, int out_size) {
  (void)n_in; (void)out_size;
  InPtrs a;
  bool interleaved = (in_sizes[2] == 4 * in_sizes[1]);
  for (int i = 0; i < 5; i++) {
    if (interleaved) {
      a.obj[i] = (const float*)d_in[1 + 2 * i];
      a.dlt[i] = (const float*)d_in[2 + 2 * i];
    } else {
      a.obj[i] = (const float*)d_in[1 + i];
      a.dlt[i] = (const float*)d_in[6 + i];
    }
  }
  const float* feats[4] = {(const float*)d_in[11], (const float*)d_in[12],
                           (const float*)d_in[13], (const float*)d_in[14]};
  float* fin = (float*)d_out;
  float* bf  = (float*)d_out + 8000;

  cudaFuncSetAttribute(sortB_kernel, cudaFuncAttributeMaxDynamicSharedMemorySize, 65536);
  cudaFuncSetAttribute(roialign_kernel, cudaFuncAttributeMaxDynamicSharedMemorySize, 50372);

  init_kernel<<<1, 256>>>();

  const int Ps[4] = {40000, 10000, 2500, 625};
  const long long offs[4] = {0, 20480000, 25600000, 26880000};
  for (int l = 0; l < 4; l++) {
    dim3 grid((Ps[l] + 31) / 32, 8, 2);
    transpose_kernel<<<grid, dim3(32, 8)>>>(feats[l], Ps[l], offs[l]);
  }

  topk_kernel<<<dim3(5, 2), 1024>>>(a);
  sortA_kernel<<<4, 1024>>>();
  sortB_kernel<<<2, 1024, 65536>>>();
  iou_kernel<<<dim3(MW, MW, 2), 64>>>();
  nms_scan_kernel<<<2, 32>>>(fin);
  roialign_kernel<<<2000, 256, 50372>>>(fin, bf);
}

// round 13
// speedup vs baseline: 1.2560x; 1.1673x over previous
#include <cuda_runtime.h>
#include <math.h>

typedef unsigned long long ull;

// ---------------------------------------------------------------------------
// constants
// ---------------------------------------------------------------------------
#define NSEL 4507
#define NPAD 8192
#define MW   71
#define MWP  72   // padded mask row (576B, 16B-aligned); word 71 always zero
#define BBOX_CLIP 4.135166556742356f
#define KU_NEGINF 0x007FFFFFu
// midpoint(0.7f, nextafterf(0.7f)): RN(inter/denom) > 0.7f  <=>  inter/denom >= IOU_MID
#define IOU_MID 0.70000001788139343262

__constant__ int   c_G[5]       = {200, 100, 50, 25, 13};
__constant__ int   c_stride[5]  = {4, 8, 16, 32, 61};
__constant__ int   c_topk[5]    = {1000, 1000, 1000, 1000, 507};
__constant__ int   c_slotoff[5] = {0, 1000, 2000, 3000, 4000};
__constant__ float c_cell[5][3][4] = {
  { {-23.f,-11.f,23.f,11.f},    {-16.f,-16.f,16.f,16.f},    {-11.f,-23.f,11.f,23.f} },
  { {-45.f,-23.f,45.f,23.f},    {-32.f,-32.f,32.f,32.f},    {-23.f,-45.f,23.f,45.f} },
  { {-91.f,-45.f,91.f,45.f},    {-64.f,-64.f,64.f,64.f},    {-45.f,-91.f,45.f,91.f} },
  { {-181.f,-91.f,181.f,91.f},  {-128.f,-128.f,128.f,128.f},{-91.f,-181.f,91.f,181.f} },
  { {-362.f,-181.f,362.f,181.f},{-256.f,-256.f,256.f,256.f},{-181.f,-362.f,181.f,362.f} },
};
__constant__ int    c_featW[4]     = {200, 100, 50, 25};
__constant__ float  c_featScale[4] = {0.25f, 0.125f, 0.0625f, 0.03125f};
__constant__ long long c_featOff[4] = {0, 20480000, 25600000, 26880000};

// ---------------------------------------------------------------------------
// device scratch
// ---------------------------------------------------------------------------
__device__ float  g_featT[27200000];
__device__ float4 g_boxes[2 * NSEL];
__device__ float  g_key[2 * NSEL];
__device__ int    g_maxc_bits[2];
__device__ ull    g_sk[2 * NPAD];
__device__ float4 g_sraw[2 * NSEL];
__device__ float4 g_soff[2 * NSEL];
__device__ ull    g_live[2][MW];
__device__ __align__(16) ull g_mask[(size_t)2 * NSEL * MWP];
__device__ int    g_lvl[2000];

struct InPtrs {
  const float* obj[5];
  const float* dlt[5];
};

__device__ __forceinline__ unsigned ordkey(float v) {
  unsigned u = __float_as_uint(v);
  return (u & 0x80000000u) ? ~u : (u | 0x80000000u);
}
__device__ __forceinline__ float inv_ordkey(unsigned u) {
  return (u & 0x80000000u) ? __uint_as_float(u & 0x7FFFFFFFu)
                           : __uint_as_float(~u);
}

// ---------------------------------------------------------------------------
// XLA-GPU f32 sigmoid emulation (logistic -> 0.5*tanh(0.5x)+0.5, Eigen tanh)
// ---------------------------------------------------------------------------
__device__ __forceinline__ float xla_tanh_f32(float x) {
  float ax = fabsf(x);
  float xc = fminf(fmaxf(x, -7.99881172180175781f), 7.99881172180175781f);
  float x2 = __fmul_rn(xc, xc);
  float p = __fmaf_rn(x2, -2.76076847742355e-16f, 2.00018790482477e-13f);
  p = __fmaf_rn(x2, p, -8.60467152213735e-11f);
  p = __fmaf_rn(x2, p, 5.12229709037114e-08f);
  p = __fmaf_rn(x2, p, 1.48572235717979e-05f);
  p = __fmaf_rn(x2, p, 6.37261928875436e-04f);
  p = __fmaf_rn(x2, p, 4.89352455891786e-03f);
  p = __fmul_rn(xc, p);
  float q = __fmaf_rn(x2, 1.19825839466702e-06f, 1.18534705686654e-04f);
  q = __fmaf_rn(x2, q, 2.26843463243900e-03f);
  q = __fmaf_rn(x2, q, 4.89352518554385e-03f);
  float r = __fdiv_rn(p, q);
  return (ax < 0.0004f) ? x : r;
}
__device__ __forceinline__ float xla_sigmoid(float x) {
  float t = xla_tanh_f32(__fmul_rn(0.5f, x));
  return __fadd_rn(__fmul_rn(0.5f, t), 0.5f);
}

// ---------------------------------------------------------------------------
// init
// ---------------------------------------------------------------------------
__global__ void init_kernel() {
  int t = threadIdx.x;
  if (t < 2) g_maxc_bits[t] = 0;
  if (t < 2 * MW) ((ull*)g_live)[t] = 0ull;
}

// ---------------------------------------------------------------------------
// transpose feats (B,256,P) -> (B,P,256)  [round-10 proven version]
// ---------------------------------------------------------------------------
__global__ void transpose_kernel(const float* __restrict__ in, int P, long long outOff) {
  __shared__ float tile[32][33];
  int b = blockIdx.z;
  int p0 = blockIdx.x * 32, c0 = blockIdx.y * 32;
  int tx = threadIdx.x, ty = threadIdx.y;
#pragma unroll
  for (int rr = 0; rr < 4; rr++) {
    int c = c0 + ty + rr * 8;
    int p = p0 + tx;
    if (p < P) tile[ty + rr * 8][tx] = in[((size_t)b * 256 + c) * P + p];
  }
  __syncthreads();
  float* out = g_featT + outOff + (size_t)b * P * 256;
#pragma unroll
  for (int rr = 0; rr < 4; rr++) {
    int p = p0 + ty + rr * 8;
    int c = c0 + tx;
    if (p < P) out[(size_t)p * 256 + c] = tile[tx][ty + rr * 8];
  }
}

// ---------------------------------------------------------------------------
// exact top-k per (level, image) + fused decode
// ---------------------------------------------------------------------------
__global__ void __launch_bounds__(1024) topk_kernel(InPtrs a) {
  int lvl = blockIdx.x, b = blockIdx.y;
  int G = c_G[lvl];
  int ncell = G * G;
  int n = 3 * ncell;
  int k = c_topk[lvl];
  const float* obj = a.obj[lvl] + (size_t)b * n;

  __shared__ int hist[256];
  __shared__ unsigned sh_prefix;
  __shared__ int sh_kc;
  __shared__ int sh_cnt;
  __shared__ ull keys[1024];

  bool vec = ((n & 3) == 0);
  int nvec = n >> 2;
  int nvec_r = (nvec + 1023) & ~1023;
  int lane = threadIdx.x & 31;

  unsigned prefix = 0;
  int kc = k;
  for (int pass = 0; pass < 4; pass++) {
    int pos = 24 - 8 * pass;
    unsigned himask = (pass == 0) ? 0u : (0xFFFFFFFFu << (pos + 8));
    for (int h = threadIdx.x; h < 256; h += 1024) hist[h] = 0;
    __syncthreads();
    if (vec) {
      const float4* o4 = (const float4*)obj;
      for (int t = threadIdx.x; t < nvec_r; t += 1024) {
        bool inb = (t < nvec);
        float4 v = inb ? o4[t] : make_float4(0.f, 0.f, 0.f, 0.f);
        float vals[4] = {v.x, v.y, v.z, v.w};
#pragma unroll
        for (int e = 0; e < 4; e++) {
          unsigned u = ordkey(vals[e]);
          bool okk = inb && ((u & himask) == prefix);
          unsigned key = okk ? ((u >> pos) & 255u) : 0xFFFFFFFFu;
          unsigned mm = __match_any_sync(0xFFFFFFFFu, key);
          int leader = __ffs(mm) - 1;
          if (okk && lane == leader)
            atomicAdd(&hist[key], __popc(mm));
        }
      }
    } else {
      for (int t = threadIdx.x; t < n; t += 1024) {
        unsigned u = ordkey(obj[t]);
        if ((u & himask) == prefix) atomicAdd(&hist[(u >> pos) & 255], 1);
      }
    }
    __syncthreads();
    if (threadIdx.x == 0) {
      int cum = 0, bin = 255;
      for (; bin >= 0; bin--) {
        int c = hist[bin];
        if (cum + c >= kc) break;
        cum += c;
      }
      sh_prefix = prefix | ((unsigned)bin << pos);
      sh_kc = kc - cum;
    }
    __syncthreads();
    prefix = sh_prefix;
    kc = sh_kc;
    __syncthreads();
  }
  unsigned T = prefix;

  for (int t = threadIdx.x; t < 1024; t += 1024) keys[t] = 0ull;
  if (threadIdx.x == 0) sh_cnt = 0;
  __syncthreads();
  if (vec) {
    const float4* o4 = (const float4*)obj;
    for (int t = threadIdx.x; t < nvec; t += 1024) {
      float4 v = o4[t];
      float vals[4] = {v.x, v.y, v.z, v.w};
#pragma unroll
      for (int e = 0; e < 4; e++) {
        unsigned u = ordkey(vals[e]);
        if (u >= T) {
          int src = t * 4 + e;
          int aa = src / ncell, yx = src - aa * ncell;
          int p = atomicAdd(&sh_cnt, 1);
          if (p < 1024)
            keys[p] = ((ull)u << 32) | (unsigned)(~(yx * 3 + aa));
        }
      }
    }
  } else {
    for (int t = threadIdx.x; t < n; t += 1024) {
      unsigned u = ordkey(obj[t]);
      if (u >= T) {
        int aa = t / ncell, yx = t - aa * ncell;
        int p = atomicAdd(&sh_cnt, 1);
        if (p < 1024)
          keys[p] = ((ull)u << 32) | (unsigned)(~(yx * 3 + aa));
      }
    }
  }
  __syncthreads();
  for (int kk = 2; kk <= 1024; kk <<= 1) {
    for (int j = kk >> 1; j > 0; j >>= 1) {
      for (int t = threadIdx.x; t < 1024; t += 1024) {
        int ixj = t ^ j;
        if (ixj > t) {
          ull A = keys[t], C = keys[ixj];
          bool desc = ((t & kk) == 0);
          if (desc ? (A < C) : (A > C)) { keys[t] = C; keys[ixj] = A; }
        }
      }
      __syncthreads();
    }
  }

  // fused decode
  int slotbase = b * NSEL + c_slotoff[lvl];
  const float* dl = a.dlt[lvl];
  size_t GG = (size_t)G * G;
  float st = (float)c_stride[lvl];
  for (int i = threadIdx.x; i < k; i += 1024) {
    ull K = keys[i];
    unsigned u = (unsigned)(K >> 32);
    int flat = (int)~(unsigned)(K & 0xFFFFFFFFull);
    float logit = inv_ordkey(u);
    int aa = flat % 3;
    int cell = flat / 3;
    int y = cell / G, x = cell - y * G;
    float sx = (float)x * st, sy = (float)y * st;
    float x1a = sx + c_cell[lvl][aa][0];
    float y1a = sy + c_cell[lvl][aa][1];
    float x2a = sx + c_cell[lvl][aa][2];
    float y2a = sy + c_cell[lvl][aa][3];
    float wa = x2a - x1a, ha = y2a - y1a;
    float cxa = x1a + 0.5f * wa, cya = y1a + 0.5f * ha;

    size_t p0 = ((size_t)b * 12 + aa * 4) * GG + (size_t)y * G + x;
    float dx = dl[p0], dy = dl[p0 + GG];
    float dw = fminf(dl[p0 + 2 * GG], BBOX_CLIP);
    float dh = fminf(dl[p0 + 3 * GG], BBOX_CLIP);

    float cx = __fadd_rn(__fmul_rn(dx, wa), cxa);
    float cy = __fadd_rn(__fmul_rn(dy, ha), cya);
    float w  = __fmul_rn(expf(dw), wa);
    float h  = __fmul_rn(expf(dh), ha);
    float hw = __fmul_rn(0.5f, w), hh = __fmul_rn(0.5f, h);
    float x1 = __fsub_rn(cx, hw), y1 = __fsub_rn(cy, hh);
    float x2 = __fadd_rn(cx, hw), y2 = __fadd_rn(cy, hh);
    x1 = fminf(fmaxf(x1, 0.f), 800.f);
    x2 = fminf(fmaxf(x2, 0.f), 800.f);
    y1 = fminf(fmaxf(y1, 0.f), 800.f);
    y2 = fminf(fmaxf(y2, 0.f), 800.f);
    bool valid = (__fsub_rn(x2, x1) >= 0.001f) && (__fsub_rn(y2, y1) >= 0.001f);

    g_boxes[slotbase + i] = make_float4(x1, y1, x2, y2);
    g_key[slotbase + i] = valid ? xla_sigmoid(logit) : -INFINITY;
    float m = fmaxf(fmaxf(x1, y1), fmaxf(x2, y2));
    atomicMax(&g_maxc_bits[b], __float_as_int(m));
  }
}

// ---------------------------------------------------------------------------
// sortA: 4 blocks; block (b, half) fully sorts its 4096 keys
// half0 descending, half1 ascending  -> concatenation is bitonic
// ---------------------------------------------------------------------------
__global__ void __launch_bounds__(1024) sortA_kernel() {
  __shared__ ull sk[4096];
  int b = blockIdx.x >> 1, half = blockIdx.x & 1;
  int base = half * 4096;
  for (int t = threadIdx.x; t < 4096; t += 1024) {
    int s = base + t;
    unsigned u = (s < NSEL) ? ordkey(g_key[b * NSEL + s]) : KU_NEGINF;
    sk[t] = ((ull)u << 32) | (unsigned)(~s);
  }
  __syncthreads();
  bool wantDesc = (half == 0);
  for (int kk = 2; kk <= 4096; kk <<= 1) {
    for (int j = kk >> 1; j > 0; j >>= 1) {
      for (int t = threadIdx.x; t < 4096; t += 1024) {
        int ixj = t ^ j;
        if (ixj > t) {
          ull A = sk[t], C = sk[ixj];
          bool descPair = (((t & kk) == 0) == wantDesc);
          if (descPair ? (A < C) : (A > C)) { sk[t] = C; sk[ixj] = A; }
        }
      }
      __syncthreads();
    }
  }
  for (int t = threadIdx.x; t < 4096; t += 1024)
    g_sk[b * NPAD + base + t] = sk[t];
}

// ---------------------------------------------------------------------------
// sortB: per-image 13-pass bitonic merge (descending) + tail
// ---------------------------------------------------------------------------
__global__ void __launch_bounds__(1024) sortB_kernel() {
  extern __shared__ ull sk[];
  int b = blockIdx.x;
  for (int t = threadIdx.x; t < NPAD; t += 1024) sk[t] = g_sk[b * NPAD + t];
  __syncthreads();
  for (int j = NPAD >> 1; j > 0; j >>= 1) {
    for (int t = threadIdx.x; t < NPAD; t += 1024) {
      int ixj = t ^ j;
      if (ixj > t) {
        ull A = sk[t], C = sk[ixj];
        if (A < C) { sk[t] = C; sk[ixj] = A; }
      }
    }
    __syncthreads();
  }
  float maxc = __int_as_float(g_maxc_bits[b]);
  float mc1 = __fadd_rn(maxc, 1.0f);
  for (int i = threadIdx.x; i < NSEL; i += 1024) {
    ull K = sk[i];
    unsigned slot = ~(unsigned)(K & 0xFFFFFFFFull);
    unsigned ku = (unsigned)(K >> 32);
    float4 bx = g_boxes[b * NSEL + slot];
    g_sraw[b * NSEL + i] = bx;
    int lvl = (slot < 1000) ? 0 : (slot < 2000) ? 1 : (slot < 3000) ? 2 : (slot < 4000) ? 3 : 4;
    float off = __fmul_rn((float)lvl, mc1);
    g_soff[b * NSEL + i] = make_float4(__fadd_rn(bx.x, off), __fadd_rn(bx.y, off),
                                       __fadd_rn(bx.z, off), __fadd_rn(bx.w, off));
    if (ku != KU_NEGINF)
      atomicOr(&g_live[b][i >> 6], 1ull << (i & 63));
  }
}

// ---------------------------------------------------------------------------
// IoU suppression bitmask. Upper triangle (cw >= rb) only; lower-tri words
// are never written and stay BSS-zero (provably never influence the scan).
// ---------------------------------------------------------------------------
__global__ void iou_kernel() {
  int cw = blockIdx.x, rb = blockIdx.y, b = blockIdx.z;
  if (cw < rb) return;
  int t = threadIdx.x;
  int i = rb * 64 + t;
  __shared__ float4 cb[64];
  __shared__ float  ca[64];
  int j0 = cw * 64;
  if (j0 + t < NSEL) {
    float4 q = g_soff[b * NSEL + j0 + t];
    cb[t] = q;
    ca[t] = __fmul_rn(__fsub_rn(q.z, q.x), __fsub_rn(q.w, q.y));
  } else {
    cb[t] = make_float4(0.f, 0.f, 0.f, 0.f);
    ca[t] = 0.f;
  }
  __syncthreads();
  if (i >= NSEL) return;
  float4 p = g_soff[b * NSEL + i];
  float pa = __fmul_rn(__fsub_rn(p.z, p.x), __fsub_rn(p.w, p.y));
  ull bits = 0;
#pragma unroll 4
  for (int jj = 0; jj < 64; jj++) {
    int j = j0 + jj;
    if (j > i && j < NSEL) {
      float4 q = cb[jj];
      float ltx = fmaxf(p.x, q.x), lty = fmaxf(p.y, q.y);
      float rbx = fminf(p.z, q.z), rby = fminf(p.w, q.w);
      float w = fmaxf(__fsub_rn(rbx, ltx), 0.f);
      float h = fmaxf(__fsub_rn(rby, lty), 0.f);
      float inter = __fmul_rn(w, h);
      if (inter > 0.f) {
        float denom = __fsub_rn(__fadd_rn(pa, ca[jj]), inter);
        if ((double)inter >= IOU_MID * (double)denom)
          bits |= 1ull << jj;
      }
    }
  }
  g_mask[((size_t)b * NSEL + i) * MWP + cw] = bits;
}

// ---------------------------------------------------------------------------
// sequential NMS scan (round-10 proven structure): per-index loop, 16-deep
// ring, monotone prefetch i+16, wait_group 15. Warp-uniform cur word (one
// shfl per 64 indices). MWP stride, 16B cp.async, fused lvl assignment.
// ---------------------------------------------------------------------------
__device__ __forceinline__ void cpasync16(void* sm, const void* gm) {
  unsigned sa = (unsigned)__cvta_generic_to_shared(sm);
  asm volatile("cp.async.ca.shared.global [%0], [%1], 16;" :: "r"(sa), "l"(gm));
}

__global__ void nms_scan_kernel(float* __restrict__ fin) {
  int b = blockIdx.x;
  int lane = threadIdx.x;
  __shared__ __align__(16) ull ring[16][MWP];
  __shared__ int keep_s[1000];

  int w0 = lane, w1 = 32 + lane, w2 = 64 + lane;  // w2 merge valid for lane<8
  ull live0 = g_live[b][w0];
  ull live1 = g_live[b][w1];
  ull live2 = (w2 < MW) ? g_live[b][w2] : 0ull;
  ull remv0 = 0, remv1 = 0, remv2 = 0;

  const ull* mbase = g_mask + (size_t)b * NSEL * MWP;
  for (int d = 0; d < 16; d++) {
    const ull* mrow = mbase + (size_t)d * MWP;
    ull* dst = ring[d];
    cpasync16(&dst[lane * 2], mrow + lane * 2);
    if (lane < 4) cpasync16(&dst[64 + lane * 2], mrow + 64 + lane * 2);
    asm volatile("cp.async.commit_group;");
  }

  ull cur = 0;
  int cnt = 0;
  for (int i = 0; i < NSEL; i++) {
    asm volatile("cp.async.wait_group 15;");
    int iw = i >> 6, ib = i & 63;
    if (ib == 0) {
      int s = iw >> 5;
      ull lv = (s == 0) ? live0 : ((s == 1) ? live1 : live2);
      ull rv = (s == 0) ? remv0 : ((s == 1) ? remv1 : remv2);
      cur = __shfl_sync(0xFFFFFFFFu, lv & ~rv, iw & 31);
    }
    if ((cur >> ib) & 1ull) {
      int slot = i & 15;
      remv0 |= ring[slot][w0];
      remv1 |= ring[slot][w1];
      if (lane < 8) remv2 |= ring[slot][w2];
      cur &= ~ring[slot][iw];
      if (lane == 0) keep_s[cnt] = i;
      cnt++;
      if (cnt >= 1000) break;
    }
    int pf = i + 16;
    if (pf < NSEL) {
      int slot = pf & 15;
      const ull* mrow = mbase + (size_t)pf * MWP;
      ull* dst = ring[slot];
      cpasync16(&dst[lane * 2], mrow + lane * 2);
      if (lane < 4) cpasync16(&dst[64 + lane * 2], mrow + 64 + lane * 2);
    }
    asm volatile("cp.async.commit_group;");
  }
  asm volatile("cp.async.wait_all;");
  __syncwarp();
  float4* fo = (float4*)fin;
  for (int j = lane; j < 1000; j += 32) {
    float4 v = make_float4(0.f, 0.f, 0.f, 0.f);
    if (j < cnt) v = g_sraw[b * NSEL + keep_s[j]];
    fo[b * 1000 + j] = v;
    float area = __fmul_rn(__fsub_rn(v.z, v.x), __fsub_rn(v.w, v.y));
    float arg = __fadd_rn(__fdiv_rn(sqrtf(area), 224.0f), 1e-6f);
    float l = floorf(__fadd_rn(4.0f, log2f(arg)));
    l = fminf(fmaxf(l, 2.0f), 5.0f);
    g_lvl[b * 1000 + j] = (int)l - 2;
  }
}

// ---------------------------------------------------------------------------
// roi align: 1 block per roi, 256 channel threads
// ---------------------------------------------------------------------------
__global__ void __launch_bounds__(256) roialign_kernel(const float* __restrict__ fin,
                                                       float* __restrict__ out) {
  extern __shared__ float outs[];  // [49][257]
  __shared__ float lx[14], hx[14], ly[14], hy[14], vxf[14], vyf[14];
  __shared__ int xl[14], xh[14], yl[14], yh[14];

  int r = blockIdx.x;
  int c = threadIdx.x;
  int li = g_lvl[r];
  float4 roi = ((const float4*)fin)[r];
  int W = c_featW[li];
  float sc = c_featScale[li];
  int b = r / 1000;

  if (c < 14) {
    float x1 = __fmul_rn(roi.x, sc), x2 = __fmul_rn(roi.z, sc);
    float bw = __fdiv_rn(fmaxf(__fsub_rn(x2, x1), 1.0f), 7.0f);
    float gg = ((float)c + 0.5f) / 2.0f;
    float xs = __fadd_rn(x1, __fmul_rn(bw, gg));
    vxf[c] = (xs >= -1.0f && xs <= (float)W) ? 1.0f : 0.0f;
    float xc = fminf(fmaxf(xs, 0.0f), (float)(W - 1));
    int xlo = (int)floorf(xc);
    xl[c] = xlo;
    xh[c] = min(xlo + 1, W - 1);
    float l = __fsub_rn(xc, (float)xlo);
    lx[c] = l;
    hx[c] = 1.0f - l;
  }
  if (c >= 16 && c < 30) {
    int q = c - 16;
    float y1 = __fmul_rn(roi.y, sc), y2 = __fmul_rn(roi.w, sc);
    float bh = __fdiv_rn(fmaxf(__fsub_rn(y2, y1), 1.0f), 7.0f);
    float gg = ((float)q + 0.5f) / 2.0f;
    float ys = __fadd_rn(y1, __fmul_rn(bh, gg));
    vyf[q] = (ys >= -1.0f && ys <= (float)W) ? 1.0f : 0.0f;
    float yc = fminf(fmaxf(ys, 0.0f), (float)(W - 1));
    int ylo = (int)floorf(yc);
    yl[q] = ylo;
    yh[q] = min(ylo + 1, W - 1);
    float l = __fsub_rn(yc, (float)ylo);
    ly[q] = l;
    hy[q] = 1.0f - l;
  }
  __syncthreads();

  const float* F = g_featT + c_featOff[li] + (size_t)b * W * W * 256 + c;
#pragma unroll 1
  for (int p = 0; p < 49; p++) {
    int py = p / 7, px = p - py * 7;
    float acc = 0.f;
#pragma unroll
    for (int sy = 0; sy < 2; sy++) {
#pragma unroll
      for (int sxi = 0; sxi < 2; sxi++) {
        int ii = py * 2 + sy, jj = px * 2 + sxi;
        int y0 = yl[ii], y1 = yh[ii], x0 = xl[jj], x1 = xh[jj];
        const float* r0 = F + (size_t)(y0 * W) * 256;
        const float* r1 = F + (size_t)(y1 * W) * 256;
        float v00 = r0[(size_t)x0 * 256];
        float v01 = r0[(size_t)x1 * 256];
        float v10 = r1[(size_t)x0 * 256];
        float v11 = r1[(size_t)x1 * 256];
        float t = (hy[ii] * hx[jj]) * v00 + (hy[ii] * lx[jj]) * v01 +
                  (ly[ii] * hx[jj]) * v10 + (ly[ii] * lx[jj]) * v11;
        acc += t * (vyf[ii] * vxf[jj]);
      }
    }
    outs[p * 257 + c] = acc * 0.25f;
  }
  __syncthreads();
  float* o = out + (size_t)r * 12544;
  for (int g = c; g < 12544; g += 256) {
    int cc = g / 49, pp = g - cc * 49;
    o[g] = outs[pp * 257 + cc];
  }
}

// ---------------------------------------------------------------------------
// launch
// ---------------------------------------------------------------------------
extern "C" void kernel_launch(void* const* d_in, const int* in_sizes, int n_in,
                              void* d_out, int out_size) {
  (void)n_in; (void)out_size;
  InPtrs a;
  bool interleaved = (in_sizes[2] == 4 * in_sizes[1]);
  for (int i = 0; i < 5; i++) {
    if (interleaved) {
      a.obj[i] = (const float*)d_in[1 + 2 * i];
      a.dlt[i] = (const float*)d_in[2 + 2 * i];
    } else {
      a.obj[i] = (const float*)d_in[1 + i];
      a.dlt[i] = (const float*)d_in[6 + i];
    }
  }
  const float* feats[4] = {(const float*)d_in[11], (const float*)d_in[12],
                           (const float*)d_in[13], (const float*)d_in[14]};
  float* fin = (float*)d_out;
  float* bf  = (float*)d_out + 8000;

  cudaFuncSetAttribute(sortB_kernel, cudaFuncAttributeMaxDynamicSharedMemorySize, 65536);
  cudaFuncSetAttribute(roialign_kernel, cudaFuncAttributeMaxDynamicSharedMemorySize, 50372);

  init_kernel<<<1, 256>>>();

  const int Ps[4] = {40000, 10000, 2500, 625};
  const long long offs[4] = {0, 20480000, 25600000, 26880000};
  for (int l = 0; l < 4; l++) {
    dim3 grid((Ps[l] + 31) / 32, 8, 2);
    transpose_kernel<<<grid, dim3(32, 8)>>>(feats[l], Ps[l], offs[l]);
  }

  topk_kernel<<<dim3(5, 2), 1024>>>(a);
  sortA_kernel<<<4, 1024>>>();
  sortB_kernel<<<2, 1024, 65536>>>();
  iou_kernel<<<dim3(MW, MW, 2), 64>>>();
  nms_scan_kernel<<<2, 32>>>(fin);
  roialign_kernel<<<2000, 256, 50372>>>(fin, bf);
}

// round 15
// speedup vs baseline: 1.2607x; 1.0038x over previous
#include <cuda_runtime.h>
#include <math.h>

typedef unsigned long long ull;

// ---------------------------------------------------------------------------
// constants
// ---------------------------------------------------------------------------
#define NSEL 4507
#define NPAD 8192
#define MW   71
#define MWP  72   // padded mask row (576B, 16B-aligned); word 71 always zero
#define BBOX_CLIP 4.135166556742356f
#define KU_NEGINF 0x007FFFFFu
// midpoint(0.7f, nextafterf(0.7f)): RN(inter/denom) > 0.7f  <=>  inter/denom >= IOU_MID
#define IOU_MID 0.70000001788139343262

__constant__ int   c_G[5]       = {200, 100, 50, 25, 13};
__constant__ int   c_stride[5]  = {4, 8, 16, 32, 61};
__constant__ int   c_topk[5]    = {1000, 1000, 1000, 1000, 507};
__constant__ int   c_slotoff[5] = {0, 1000, 2000, 3000, 4000};
__constant__ float c_cell[5][3][4] = {
  { {-23.f,-11.f,23.f,11.f},    {-16.f,-16.f,16.f,16.f},    {-11.f,-23.f,11.f,23.f} },
  { {-45.f,-23.f,45.f,23.f},    {-32.f,-32.f,32.f,32.f},    {-23.f,-45.f,23.f,45.f} },
  { {-91.f,-45.f,91.f,45.f},    {-64.f,-64.f,64.f,64.f},    {-45.f,-91.f,45.f,91.f} },
  { {-181.f,-91.f,181.f,91.f},  {-128.f,-128.f,128.f,128.f},{-91.f,-181.f,91.f,181.f} },
  { {-362.f,-181.f,362.f,181.f},{-256.f,-256.f,256.f,256.f},{-181.f,-362.f,181.f,362.f} },
};
__constant__ int    c_featW[4]     = {200, 100, 50, 25};
__constant__ float  c_featScale[4] = {0.25f, 0.125f, 0.0625f, 0.03125f};
__constant__ long long c_featOff[4] = {0, 20480000, 25600000, 26880000};

// ---------------------------------------------------------------------------
// device scratch
// ---------------------------------------------------------------------------
__device__ __align__(16) float g_featT[27200000];
__device__ float4 g_boxes[2 * NSEL];
__device__ float  g_key[2 * NSEL];
__device__ int    g_maxc_bits[2];
__device__ ull    g_sk[2 * NPAD];
__device__ float4 g_sraw[2 * NSEL];
__device__ float4 g_soff[2 * NSEL];
__device__ ull    g_live[2][MW];
__device__ __align__(16) ull g_mask[(size_t)2 * NSEL * MWP];
__device__ int    g_lvl[2000];

struct InPtrs {
  const float* obj[5];
  const float* dlt[5];
};

__device__ __forceinline__ unsigned ordkey(float v) {
  unsigned u = __float_as_uint(v);
  return (u & 0x80000000u) ? ~u : (u | 0x80000000u);
}
__device__ __forceinline__ float inv_ordkey(unsigned u) {
  return (u & 0x80000000u) ? __uint_as_float(u & 0x7FFFFFFFu)
                           : __uint_as_float(~u);
}

// ---------------------------------------------------------------------------
// XLA-GPU f32 sigmoid emulation (logistic -> 0.5*tanh(0.5x)+0.5, Eigen tanh)
// ---------------------------------------------------------------------------
__device__ __forceinline__ float xla_tanh_f32(float x) {
  float ax = fabsf(x);
  float xc = fminf(fmaxf(x, -7.99881172180175781f), 7.99881172180175781f);
  float x2 = __fmul_rn(xc, xc);
  float p = __fmaf_rn(x2, -2.76076847742355e-16f, 2.00018790482477e-13f);
  p = __fmaf_rn(x2, p, -8.60467152213735e-11f);
  p = __fmaf_rn(x2, p, 5.12229709037114e-08f);
  p = __fmaf_rn(x2, p, 1.48572235717979e-05f);
  p = __fmaf_rn(x2, p, 6.37261928875436e-04f);
  p = __fmaf_rn(x2, p, 4.89352455891786e-03f);
  p = __fmul_rn(xc, p);
  float q = __fmaf_rn(x2, 1.19825839466702e-06f, 1.18534705686654e-04f);
  q = __fmaf_rn(x2, q, 2.26843463243900e-03f);
  q = __fmaf_rn(x2, q, 4.89352518554385e-03f);
  float r = __fdiv_rn(p, q);
  return (ax < 0.0004f) ? x : r;
}
__device__ __forceinline__ float xla_sigmoid(float x) {
  float t = xla_tanh_f32(__fmul_rn(0.5f, x));
  return __fadd_rn(__fmul_rn(0.5f, t), 0.5f);
}

// ---------------------------------------------------------------------------
// init
// ---------------------------------------------------------------------------
__global__ void init_kernel() {
  int t = threadIdx.x;
  if (t < 2) g_maxc_bits[t] = 0;
  if (t < 2 * MW) ((ull*)g_live)[t] = 0ull;
}

// ---------------------------------------------------------------------------
// fast transpose (levels with P % 4 == 0): (B,256,P) -> (B,P,256),
// float4 both directions. tile: 32 channels x 128 positions, 256 threads.
// ---------------------------------------------------------------------------
__global__ void __launch_bounds__(256) transpose_vec_kernel(const float* __restrict__ in,
                                                            int P, long long outOff) {
  __shared__ float tile[32][129];
  int b = blockIdx.z;
  int p0 = blockIdx.x * 128, c0 = blockIdx.y * 32;
  int tx = threadIdx.x & 31, ty = threadIdx.x >> 5;  // tx 0..31, ty 0..7

#pragma unroll
  for (int rr = 0; rr < 4; rr++) {
    int cc = ty + rr * 8;
    const float* src = in + ((size_t)b * 256 + c0 + cc) * P;
    int p = p0 + tx * 4;
    if (p + 3 < P) {
      float4 v = *(const float4*)(src + p);
      tile[cc][tx * 4 + 0] = v.x;
      tile[cc][tx * 4 + 1] = v.y;
      tile[cc][tx * 4 + 2] = v.z;
      tile[cc][tx * 4 + 3] = v.w;
    } else {
#pragma unroll
      for (int k = 0; k < 4; k++)
        if (p + k < P) tile[cc][tx * 4 + k] = src[p + k];
    }
  }
  __syncthreads();
  float* out = g_featT + outOff + (size_t)b * P * 256;
#pragma unroll
  for (int rr = 0; rr < 4; rr++) {
    int pp = tx + 32 * rr;
    int p = p0 + pp;
    if (p < P) {
      float4 v;
      v.x = tile[ty * 4 + 0][pp];
      v.y = tile[ty * 4 + 1][pp];
      v.z = tile[ty * 4 + 2][pp];
      v.w = tile[ty * 4 + 3][pp];
      *(float4*)(out + (size_t)p * 256 + c0 + ty * 4) = v;
    }
  }
}

// scalar transpose for level 3 (P=625, rows not 16B-aligned)
__global__ void transpose_scalar_kernel(const float* __restrict__ in, int P, long long outOff) {
  __shared__ float tile[32][33];
  int b = blockIdx.z;
  int p0 = blockIdx.x * 32, c0 = blockIdx.y * 32;
  int tx = threadIdx.x, ty = threadIdx.y;
#pragma unroll
  for (int rr = 0; rr < 4; rr++) {
    int c = c0 + ty + rr * 8;
    int p = p0 + tx;
    if (p < P) tile[ty + rr * 8][tx] = in[((size_t)b * 256 + c) * P + p];
  }
  __syncthreads();
  float* out = g_featT + outOff + (size_t)b * P * 256;
#pragma unroll
  for (int rr = 0; rr < 4; rr++) {
    int p = p0 + ty + rr * 8;
    int c = c0 + tx;
    if (p < P) out[(size_t)p * 256 + c] = tile[tx][ty + rr * 8];
  }
}

// ---------------------------------------------------------------------------
// exact top-k per (level, image) + fused decode
// ---------------------------------------------------------------------------
__global__ void __launch_bounds__(1024) topk_kernel(InPtrs a) {
  int lvl = blockIdx.x, b = blockIdx.y;
  int G = c_G[lvl];
  int ncell = G * G;
  int n = 3 * ncell;
  int k = c_topk[lvl];
  const float* obj = a.obj[lvl] + (size_t)b * n;

  __shared__ int hist[256];
  __shared__ unsigned sh_prefix;
  __shared__ int sh_kc;
  __shared__ int sh_cnt;
  __shared__ ull keys[1024];

  bool vec = ((n & 3) == 0);
  int nvec = n >> 2;
  int nvec_r = (nvec + 1023) & ~1023;
  int lane = threadIdx.x & 31;

  unsigned prefix = 0;
  int kc = k;
  for (int pass = 0; pass < 4; pass++) {
    int pos = 24 - 8 * pass;
    unsigned himask = (pass == 0) ? 0u : (0xFFFFFFFFu << (pos + 8));
    for (int h = threadIdx.x; h < 256; h += 1024) hist[h] = 0;
    __syncthreads();
    if (vec) {
      const float4* o4 = (const float4*)obj;
      for (int t = threadIdx.x; t < nvec_r; t += 1024) {
        bool inb = (t < nvec);
        float4 v = inb ? o4[t] : make_float4(0.f, 0.f, 0.f, 0.f);
        float vals[4] = {v.x, v.y, v.z, v.w};
#pragma unroll
        for (int e = 0; e < 4; e++) {
          unsigned u = ordkey(vals[e]);
          bool okk = inb && ((u & himask) == prefix);
          unsigned key = okk ? ((u >> pos) & 255u) : 0xFFFFFFFFu;
          unsigned mm = __match_any_sync(0xFFFFFFFFu, key);
          int leader = __ffs(mm) - 1;
          if (okk && lane == leader)
            atomicAdd(&hist[key], __popc(mm));
        }
      }
    } else {
      for (int t = threadIdx.x; t < n; t += 1024) {
        unsigned u = ordkey(obj[t]);
        if ((u & himask) == prefix) atomicAdd(&hist[(u >> pos) & 255], 1);
      }
    }
    __syncthreads();
    if (threadIdx.x == 0) {
      int cum = 0, bin = 255;
      for (; bin >= 0; bin--) {
        int c = hist[bin];
        if (cum + c >= kc) break;
        cum += c;
      }
      sh_prefix = prefix | ((unsigned)bin << pos);
      sh_kc = kc - cum;
    }
    __syncthreads();
    prefix = sh_prefix;
    kc = sh_kc;
    __syncthreads();
  }
  unsigned T = prefix;

  for (int t = threadIdx.x; t < 1024; t += 1024) keys[t] = 0ull;
  if (threadIdx.x == 0) sh_cnt = 0;
  __syncthreads();
  if (vec) {
    const float4* o4 = (const float4*)obj;
    for (int t = threadIdx.x; t < nvec; t += 1024) {
      float4 v = o4[t];
      float vals[4] = {v.x, v.y, v.z, v.w};
#pragma unroll
      for (int e = 0; e < 4; e++) {
        unsigned u = ordkey(vals[e]);
        if (u >= T) {
          int src = t * 4 + e;
          int aa = src / ncell, yx = src - aa * ncell;
          int p = atomicAdd(&sh_cnt, 1);
          if (p < 1024)
            keys[p] = ((ull)u << 32) | (unsigned)(~(yx * 3 + aa));
        }
      }
    }
  } else {
    for (int t = threadIdx.x; t < n; t += 1024) {
      unsigned u = ordkey(obj[t]);
      if (u >= T) {
        int aa = t / ncell, yx = t - aa * ncell;
        int p = atomicAdd(&sh_cnt, 1);
        if (p < 1024)
          keys[p] = ((ull)u << 32) | (unsigned)(~(yx * 3 + aa));
      }
    }
  }
  __syncthreads();
  for (int kk = 2; kk <= 1024; kk <<= 1) {
    for (int j = kk >> 1; j > 0; j >>= 1) {
      for (int t = threadIdx.x; t < 1024; t += 1024) {
        int ixj = t ^ j;
        if (ixj > t) {
          ull A = keys[t], C = keys[ixj];
          bool desc = ((t & kk) == 0);
          if (desc ? (A < C) : (A > C)) { keys[t] = C; keys[ixj] = A; }
        }
      }
      __syncthreads();
    }
  }

  // fused decode
  int slotbase = b * NSEL + c_slotoff[lvl];
  const float* dl = a.dlt[lvl];
  size_t GG = (size_t)G * G;
  float st = (float)c_stride[lvl];
  for (int i = threadIdx.x; i < k; i += 1024) {
    ull K = keys[i];
    unsigned u = (unsigned)(K >> 32);
    int flat = (int)~(unsigned)(K & 0xFFFFFFFFull);
    float logit = inv_ordkey(u);
    int aa = flat % 3;
    int cell = flat / 3;
    int y = cell / G, x = cell - y * G;
    float sx = (float)x * st, sy = (float)y * st;
    float x1a = sx + c_cell[lvl][aa][0];
    float y1a = sy + c_cell[lvl][aa][1];
    float x2a = sx + c_cell[lvl][aa][2];
    float y2a = sy + c_cell[lvl][aa][3];
    float wa = x2a - x1a, ha = y2a - y1a;
    float cxa = x1a + 0.5f * wa, cya = y1a + 0.5f * ha;

    size_t p0 = ((size_t)b * 12 + aa * 4) * GG + (size_t)y * G + x;
    float dx = dl[p0], dy = dl[p0 + GG];
    float dw = fminf(dl[p0 + 2 * GG], BBOX_CLIP);
    float dh = fminf(dl[p0 + 3 * GG], BBOX_CLIP);

    float cx = __fadd_rn(__fmul_rn(dx, wa), cxa);
    float cy = __fadd_rn(__fmul_rn(dy, ha), cya);
    float w  = __fmul_rn(expf(dw), wa);
    float h  = __fmul_rn(expf(dh), ha);
    float hw = __fmul_rn(0.5f, w), hh = __fmul_rn(0.5f, h);
    float x1 = __fsub_rn(cx, hw), y1 = __fsub_rn(cy, hh);
    float x2 = __fadd_rn(cx, hw), y2 = __fadd_rn(cy, hh);
    x1 = fminf(fmaxf(x1, 0.f), 800.f);
    x2 = fminf(fmaxf(x2, 0.f), 800.f);
    y1 = fminf(fmaxf(y1, 0.f), 800.f);
    y2 = fminf(fmaxf(y2, 0.f), 800.f);
    bool valid = (__fsub_rn(x2, x1) >= 0.001f) && (__fsub_rn(y2, y1) >= 0.001f);

    g_boxes[slotbase + i] = make_float4(x1, y1, x2, y2);
    g_key[slotbase + i] = valid ? xla_sigmoid(logit) : -INFINITY;
    float m = fmaxf(fmaxf(x1, y1), fmaxf(x2, y2));
    atomicMax(&g_maxc_bits[b], __float_as_int(m));
  }
}

// ---------------------------------------------------------------------------
// sortA: 4 blocks; block (b, half) fully sorts its 4096 keys
// half0 descending, half1 ascending  -> concatenation is bitonic
// ---------------------------------------------------------------------------
__global__ void __launch_bounds__(1024) sortA_kernel() {
  __shared__ ull sk[4096];
  int b = blockIdx.x >> 1, half = blockIdx.x & 1;
  int base = half * 4096;
  for (int t = threadIdx.x; t < 4096; t += 1024) {
    int s = base + t;
    unsigned u = (s < NSEL) ? ordkey(g_key[b * NSEL + s]) : KU_NEGINF;
    sk[t] = ((ull)u << 32) | (unsigned)(~s);
  }
  __syncthreads();
  bool wantDesc = (half == 0);
  for (int kk = 2; kk <= 4096; kk <<= 1) {
    for (int j = kk >> 1; j > 0; j >>= 1) {
      for (int t = threadIdx.x; t < 4096; t += 1024) {
        int ixj = t ^ j;
        if (ixj > t) {
          ull A = sk[t], C = sk[ixj];
          bool descPair = (((t & kk) == 0) == wantDesc);
          if (descPair ? (A < C) : (A > C)) { sk[t] = C; sk[ixj] = A; }
        }
      }
      __syncthreads();
    }
  }
  for (int t = threadIdx.x; t < 4096; t += 1024)
    g_sk[b * NPAD + base + t] = sk[t];
}

// ---------------------------------------------------------------------------
// sortB: per-image 13-pass bitonic merge (descending) + tail
// ---------------------------------------------------------------------------
__global__ void __launch_bounds__(1024) sortB_kernel() {
  extern __shared__ ull sk[];
  int b = blockIdx.x;
  for (int t = threadIdx.x; t < NPAD; t += 1024) sk[t] = g_sk[b * NPAD + t];
  __syncthreads();
  for (int j = NPAD >> 1; j > 0; j >>= 1) {
    for (int t = threadIdx.x; t < NPAD; t += 1024) {
      int ixj = t ^ j;
      if (ixj > t) {
        ull A = sk[t], C = sk[ixj];
        if (A < C) { sk[t] = C; sk[ixj] = A; }
      }
    }
    __syncthreads();
  }
  float maxc = __int_as_float(g_maxc_bits[b]);
  float mc1 = __fadd_rn(maxc, 1.0f);
  for (int i = threadIdx.x; i < NSEL; i += 1024) {
    ull K = sk[i];
    unsigned slot = ~(unsigned)(K & 0xFFFFFFFFull);
    unsigned ku = (unsigned)(K >> 32);
    float4 bx = g_boxes[b * NSEL + slot];
    g_sraw[b * NSEL + i] = bx;
    int lvl = (slot < 1000) ? 0 : (slot < 2000) ? 1 : (slot < 3000) ? 2 : (slot < 4000) ? 3 : 4;
    float off = __fmul_rn((float)lvl, mc1);
    g_soff[b * NSEL + i] = make_float4(__fadd_rn(bx.x, off), __fadd_rn(bx.y, off),
                                       __fadd_rn(bx.z, off), __fadd_rn(bx.w, off));
    if (ku != KU_NEGINF)
      atomicOr(&g_live[b][i >> 6], 1ull << (i & 63));
  }
}

// ---------------------------------------------------------------------------
// IoU suppression bitmask. Upper triangle (cw >= rb) only; lower-tri words
// are never written and stay BSS-zero (provably never influence the scan).
// ---------------------------------------------------------------------------
__global__ void iou_kernel() {
  int cw = blockIdx.x, rb = blockIdx.y, b = blockIdx.z;
  if (cw < rb) return;
  int t = threadIdx.x;
  int i = rb * 64 + t;
  __shared__ float4 cb[64];
  __shared__ float  ca[64];
  int j0 = cw * 64;
  if (j0 + t < NSEL) {
    float4 q = g_soff[b * NSEL + j0 + t];
    cb[t] = q;
    ca[t] = __fmul_rn(__fsub_rn(q.z, q.x), __fsub_rn(q.w, q.y));
  } else {
    cb[t] = make_float4(0.f, 0.f, 0.f, 0.f);
    ca[t] = 0.f;
  }
  __syncthreads();
  if (i >= NSEL) return;
  float4 p = g_soff[b * NSEL + i];
  float pa = __fmul_rn(__fsub_rn(p.z, p.x), __fsub_rn(p.w, p.y));
  ull bits = 0;
#pragma unroll 4
  for (int jj = 0; jj < 64; jj++) {
    int j = j0 + jj;
    if (j > i && j < NSEL) {
      float4 q = cb[jj];
      float ltx = fmaxf(p.x, q.x), lty = fmaxf(p.y, q.y);
      float rbx = fminf(p.z, q.z), rby = fminf(p.w, q.w);
      float w = fmaxf(__fsub_rn(rbx, ltx), 0.f);
      float h = fmaxf(__fsub_rn(rby, lty), 0.f);
      float inter = __fmul_rn(w, h);
      if (inter > 0.f) {
        float denom = __fsub_rn(__fadd_rn(pa, ca[jj]), inter);
        if ((double)inter >= IOU_MID * (double)denom)
          bits |= 1ull << jj;
      }
    }
  }
  g_mask[((size_t)b * NSEL + i) * MWP + cw] = bits;
}

// ---------------------------------------------------------------------------
// sequential NMS scan (round-10 proven structure): per-index loop, 16-deep
// ring, monotone prefetch i+16, wait_group 15. Warp-uniform cur word (one
// shfl per 64 indices). MWP stride, 16B cp.async, fused lvl assignment.
// ---------------------------------------------------------------------------
__device__ __forceinline__ void cpasync16(void* sm, const void* gm) {
  unsigned sa = (unsigned)__cvta_generic_to_shared(sm);
  asm volatile("cp.async.ca.shared.global [%0], [%1], 16;" :: "r"(sa), "l"(gm));
}

__global__ void nms_scan_kernel(float* __restrict__ fin) {
  int b = blockIdx.x;
  int lane = threadIdx.x;
  __shared__ __align__(16) ull ring[16][MWP];
  __shared__ int keep_s[1000];

  int w0 = lane, w1 = 32 + lane, w2 = 64 + lane;  // w2 merge valid for lane<8
  ull live0 = g_live[b][w0];
  ull live1 = g_live[b][w1];
  ull live2 = (w2 < MW) ? g_live[b][w2] : 0ull;
  ull remv0 = 0, remv1 = 0, remv2 = 0;

  const ull* mbase = g_mask + (size_t)b * NSEL * MWP;
  for (int d = 0; d < 16; d++) {
    const ull* mrow = mbase + (size_t)d * MWP;
    ull* dst = ring[d];
    cpasync16(&dst[lane * 2], mrow + lane * 2);
    if (lane < 4) cpasync16(&dst[64 + lane * 2], mrow + 64 + lane * 2);
    asm volatile("cp.async.commit_group;");
  }

  ull cur = 0;
  int cnt = 0;
  for (int i = 0; i < NSEL; i++) {
    asm volatile("cp.async.wait_group 15;");
    int iw = i >> 6, ib = i & 63;
    if (ib == 0) {
      int s = iw >> 5;
      ull lv = (s == 0) ? live0 : ((s == 1) ? live1 : live2);
      ull rv = (s == 0) ? remv0 : ((s == 1) ? remv1 : remv2);
      cur = __shfl_sync(0xFFFFFFFFu, lv & ~rv, iw & 31);
    }
    if ((cur >> ib) & 1ull) {
      int slot = i & 15;
      remv0 |= ring[slot][w0];
      remv1 |= ring[slot][w1];
      if (lane < 8) remv2 |= ring[slot][w2];
      cur &= ~ring[slot][iw];
      if (lane == 0) keep_s[cnt] = i;
      cnt++;
      if (cnt >= 1000) break;
    }
    int pf = i + 16;
    if (pf < NSEL) {
      int slot = pf & 15;
      const ull* mrow = mbase + (size_t)pf * MWP;
      ull* dst = ring[slot];
      cpasync16(&dst[lane * 2], mrow + lane * 2);
      if (lane < 4) cpasync16(&dst[64 + lane * 2], mrow + 64 + lane * 2);
    }
    asm volatile("cp.async.commit_group;");
  }
  asm volatile("cp.async.wait_all;");
  __syncwarp();
  float4* fo = (float4*)fin;
  for (int j = lane; j < 1000; j += 32) {
    float4 v = make_float4(0.f, 0.f, 0.f, 0.f);
    if (j < cnt) v = g_sraw[b * NSEL + keep_s[j]];
    fo[b * 1000 + j] = v;
    float area = __fmul_rn(__fsub_rn(v.z, v.x), __fsub_rn(v.w, v.y));
    float arg = __fadd_rn(__fdiv_rn(sqrtf(area), 224.0f), 1e-6f);
    float l = floorf(__fadd_rn(4.0f, log2f(arg)));
    l = fminf(fmaxf(l, 2.0f), 5.0f);
    g_lvl[b * 1000 + j] = (int)l - 2;
  }
}

// ---------------------------------------------------------------------------
// roi align: 1 block per roi, 256 channel threads
// ---------------------------------------------------------------------------
__global__ void __launch_bounds__(256) roialign_kernel(const float* __restrict__ fin,
                                                       float* __restrict__ out) {
  extern __shared__ float outs[];  // [49][257]
  __shared__ float lx[14], hx[14], ly[14], hy[14], vxf[14], vyf[14];
  __shared__ int xl[14], xh[14], yl[14], yh[14];

  int r = blockIdx.x;
  int c = threadIdx.x;
  int li = g_lvl[r];
  float4 roi = ((const float4*)fin)[r];
  int W = c_featW[li];
  float sc = c_featScale[li];
  int b = r / 1000;

  if (c < 14) {
    float x1 = __fmul_rn(roi.x, sc), x2 = __fmul_rn(roi.z, sc);
    float bw = __fdiv_rn(fmaxf(__fsub_rn(x2, x1), 1.0f), 7.0f);
    float gg = ((float)c + 0.5f) / 2.0f;
    float xs = __fadd_rn(x1, __fmul_rn(bw, gg));
    vxf[c] = (xs >= -1.0f && xs <= (float)W) ? 1.0f : 0.0f;
    float xc = fminf(fmaxf(xs, 0.0f), (float)(W - 1));
    int xlo = (int)floorf(xc);
    xl[c] = xlo;
    xh[c] = min(xlo + 1, W - 1);
    float l = __fsub_rn(xc, (float)xlo);
    lx[c] = l;
    hx[c] = 1.0f - l;
  }
  if (c >= 16 && c < 30) {
    int q = c - 16;
    float y1 = __fmul_rn(roi.y, sc), y2 = __fmul_rn(roi.w, sc);
    float bh = __fdiv_rn(fmaxf(__fsub_rn(y2, y1), 1.0f), 7.0f);
    float gg = ((float)q + 0.5f) / 2.0f;
    float ys = __fadd_rn(y1, __fmul_rn(bh, gg));
    vyf[q] = (ys >= -1.0f && ys <= (float)W) ? 1.0f : 0.0f;
    float yc = fminf(fmaxf(ys, 0.0f), (float)(W - 1));
    int ylo = (int)floorf(yc);
    yl[q] = ylo;
    yh[q] = min(ylo + 1, W - 1);
    float l = __fsub_rn(yc, (float)ylo);
    ly[q] = l;
    hy[q] = 1.0f - l;
  }
  __syncthreads();

  const float* F = g_featT + c_featOff[li] + (size_t)b * W * W * 256 + c;
#pragma unroll 1
  for (int p = 0; p < 49; p++) {
    int py = p / 7, px = p - py * 7;
    float acc = 0.f;
#pragma unroll
    for (int sy = 0; sy < 2; sy++) {
#pragma unroll
      for (int sxi = 0; sxi < 2; sxi++) {
        int ii = py * 2 + sy, jj = px * 2 + sxi;
        int y0 = yl[ii], y1 = yh[ii], x0 = xl[jj], x1 = xh[jj];
        const float* r0 = F + (size_t)(y0 * W) * 256;
        const float* r1 = F + (size_t)(y1 * W) * 256;
        float v00 = r0[(size_t)x0 * 256];
        float v01 = r0[(size_t)x1 * 256];
        float v10 = r1[(size_t)x0 * 256];
        float v11 = r1[(size_t)x1 * 256];
        float t = (hy[ii] * hx[jj]) * v00 + (hy[ii] * lx[jj]) * v01 +
                  (ly[ii] * hx[jj]) * v10 + (ly[ii] * lx[jj]) * v11;
        acc += t * (vyf[ii] * vxf[jj]);
      }
    }
    outs[p * 257 + c] = acc * 0.25f;
  }
  __syncthreads();
  float* o = out + (size_t)r * 12544;
  for (int g = c; g < 12544; g += 256) {
    int cc = g / 49, pp = g - cc * 49;
    o[g] = outs[pp * 257 + cc];
  }
}

// ---------------------------------------------------------------------------
// launch: transposes forked onto a side stream, joined before roialign
// ---------------------------------------------------------------------------
extern "C" void kernel_launch(void* const* d_in, const int* in_sizes, int n_in,
                              void* d_out, int out_size) {
  (void)n_in; (void)out_size;
  static cudaStream_t s_side = 0;
  static cudaEvent_t  s_fork = 0, s_join = 0;
  if (!s_side) {
    cudaStreamCreateWithFlags(&s_side, cudaStreamNonBlocking);
    cudaEventCreateWithFlags(&s_fork, cudaEventDisableTiming);
    cudaEventCreateWithFlags(&s_join, cudaEventDisableTiming);
  }

  InPtrs a;
  bool interleaved = (in_sizes[2] == 4 * in_sizes[1]);
  for (int i = 0; i < 5; i++) {
    if (interleaved) {
      a.obj[i] = (const float*)d_in[1 + 2 * i];
      a.dlt[i] = (const float*)d_in[2 + 2 * i];
    } else {
      a.obj[i] = (const float*)d_in[1 + i];
      a.dlt[i] = (const float*)d_in[6 + i];
    }
  }
  const float* feats[4] = {(const float*)d_in[11], (const float*)d_in[12],
                           (const float*)d_in[13], (const float*)d_in[14]};
  float* fin = (float*)d_out;
  float* bf  = (float*)d_out + 8000;

  cudaFuncSetAttribute(sortB_kernel, cudaFuncAttributeMaxDynamicSharedMemorySize, 65536);
  cudaFuncSetAttribute(roialign_kernel, cudaFuncAttributeMaxDynamicSharedMemorySize, 50372);

  init_kernel<<<1, 256>>>();

  // fork: transposes on side stream
  cudaEventRecord(s_fork, 0);
  cudaStreamWaitEvent(s_side, s_fork, 0);
  const int Ps[4] = {40000, 10000, 2500, 625};
  const long long offs[4] = {0, 20480000, 25600000, 26880000};
  for (int l = 0; l < 3; l++) {  // P % 4 == 0: vector transpose
    dim3 grid((Ps[l] + 127) / 128, 8, 2);
    transpose_vec_kernel<<<grid, 256, 0, s_side>>>(feats[l], Ps[l], offs[l]);
  }
  {  // level 3 (P=625, rows not 16B aligned): scalar transpose
    dim3 grid((Ps[3] + 31) / 32, 8, 2);
    transpose_scalar_kernel<<<grid, dim3(32, 8), 0, s_side>>>(feats[3], Ps[3], offs[3]);
  }
  cudaEventRecord(s_join, s_side);

  // main chain on default stream
  topk_kernel<<<dim3(5, 2), 1024>>>(a);
  sortA_kernel<<<4, 1024>>>();
  sortB_kernel<<<2, 1024, 65536>>>();
  iou_kernel<<<dim3(MW, MW, 2), 64>>>();
  nms_scan_kernel<<<2, 32>>>(fin);

  // join before roialign (needs g_featT)
  cudaStreamWaitEvent(0, s_join, 0);
  roialign_kernel<<<2000, 256, 50372>>>(fin, bf);
}

// round 17
// speedup vs baseline: 1.4491x; 1.1494x over previous
#include <cuda_runtime.h>
#include <math.h>

typedef unsigned long long ull;

// ---------------------------------------------------------------------------
// constants
// ---------------------------------------------------------------------------
#define NSEL 4507
#define NPAD 8192
#define MW   71
#define MWP  72   // padded mask row (576B, 16B-aligned); word 71 always zero
#define BBOX_CLIP 4.135166556742356f
#define KU_NEGINF 0x007FFFFFu
#define IOU_MID 0.70000001788139343262

__constant__ int   c_G[5]       = {200, 100, 50, 25, 13};
__constant__ int   c_stride[5]  = {4, 8, 16, 32, 61};
__constant__ int   c_topk[5]    = {1000, 1000, 1000, 1000, 507};
__constant__ int   c_slotoff[5] = {0, 1000, 2000, 3000, 4000};
__constant__ float c_cell[5][3][4] = {
  { {-23.f,-11.f,23.f,11.f},    {-16.f,-16.f,16.f,16.f},    {-11.f,-23.f,11.f,23.f} },
  { {-45.f,-23.f,45.f,23.f},    {-32.f,-32.f,32.f,32.f},    {-23.f,-45.f,23.f,45.f} },
  { {-91.f,-45.f,91.f,45.f},    {-64.f,-64.f,64.f,64.f},    {-45.f,-91.f,45.f,91.f} },
  { {-181.f,-91.f,181.f,91.f},  {-128.f,-128.f,128.f,128.f},{-91.f,-181.f,91.f,181.f} },
  { {-362.f,-181.f,362.f,181.f},{-256.f,-256.f,256.f,256.f},{-181.f,-362.f,181.f,362.f} },
};
__constant__ int    c_featW[4]     = {200, 100, 50, 25};
__constant__ float  c_featScale[4] = {0.25f, 0.125f, 0.0625f, 0.03125f};
__constant__ long long c_featOff[4] = {0, 20480000, 25600000, 26880000};

// ---------------------------------------------------------------------------
// device scratch
// ---------------------------------------------------------------------------
__device__ __align__(16) float g_featT[27200000];
__device__ float4 g_boxes[2 * NSEL];
__device__ float  g_key[2 * NSEL];
__device__ int    g_maxc_bits[2];
__device__ ull    g_sk[2 * NPAD];
__device__ float4 g_sraw[2 * NSEL];
__device__ float4 g_soff[2 * NSEL];
__device__ ull    g_live[2][MW];
__device__ __align__(16) ull g_mask[(size_t)2 * NSEL * MWP];
__device__ int    g_lvl[2000];

struct InPtrs {
  const float* obj[5];
  const float* dlt[5];
};

__device__ __forceinline__ unsigned ordkey(float v) {
  unsigned u = __float_as_uint(v);
  return (u & 0x80000000u) ? ~u : (u | 0x80000000u);
}
__device__ __forceinline__ float inv_ordkey(unsigned u) {
  return (u & 0x80000000u) ? __uint_as_float(u & 0x7FFFFFFFu)
                           : __uint_as_float(~u);
}

// ---------------------------------------------------------------------------
// XLA-GPU f32 sigmoid emulation (logistic -> 0.5*tanh(0.5x)+0.5, Eigen tanh)
// ---------------------------------------------------------------------------
__device__ __forceinline__ float xla_tanh_f32(float x) {
  float ax = fabsf(x);
  float xc = fminf(fmaxf(x, -7.99881172180175781f), 7.99881172180175781f);
  float x2 = __fmul_rn(xc, xc);
  float p = __fmaf_rn(x2, -2.76076847742355e-16f, 2.00018790482477e-13f);
  p = __fmaf_rn(x2, p, -8.60467152213735e-11f);
  p = __fmaf_rn(x2, p, 5.12229709037114e-08f);
  p = __fmaf_rn(x2, p, 1.48572235717979e-05f);
  p = __fmaf_rn(x2, p, 6.37261928875436e-04f);
  p = __fmaf_rn(x2, p, 4.89352455891786e-03f);
  p = __fmul_rn(xc, p);
  float q = __fmaf_rn(x2, 1.19825839466702e-06f, 1.18534705686654e-04f);
  q = __fmaf_rn(x2, q, 2.26843463243900e-03f);
  q = __fmaf_rn(x2, q, 4.89352518554385e-03f);
  float r = __fdiv_rn(p, q);
  return (ax < 0.0004f) ? x : r;
}
__device__ __forceinline__ float xla_sigmoid(float x) {
  float t = xla_tanh_f32(__fmul_rn(0.5f, x));
  return __fadd_rn(__fmul_rn(0.5f, t), 0.5f);
}

// ---------------------------------------------------------------------------
// init
// ---------------------------------------------------------------------------
__global__ void init_kernel() {
  int t = threadIdx.x;
  if (t < 2) g_maxc_bits[t] = 0;
  if (t < 2 * MW) ((ull*)g_live)[t] = 0ull;
}

// ---------------------------------------------------------------------------
// fast transpose (P % 4 == 0): (B,256,P) -> (B,P,256), float4 both dirs
// ---------------------------------------------------------------------------
__global__ void __launch_bounds__(256) transpose_vec_kernel(const float* __restrict__ in,
                                                            int P, long long outOff) {
  __shared__ float tile[32][129];
  int b = blockIdx.z;
  int p0 = blockIdx.x * 128, c0 = blockIdx.y * 32;
  int tx = threadIdx.x & 31, ty = threadIdx.x >> 5;

#pragma unroll
  for (int rr = 0; rr < 4; rr++) {
    int cc = ty + rr * 8;
    const float* src = in + ((size_t)b * 256 + c0 + cc) * P;
    int p = p0 + tx * 4;
    if (p + 3 < P) {
      float4 v = *(const float4*)(src + p);
      tile[cc][tx * 4 + 0] = v.x;
      tile[cc][tx * 4 + 1] = v.y;
      tile[cc][tx * 4 + 2] = v.z;
      tile[cc][tx * 4 + 3] = v.w;
    } else {
#pragma unroll
      for (int k = 0; k < 4; k++)
        if (p + k < P) tile[cc][tx * 4 + k] = src[p + k];
    }
  }
  __syncthreads();
  float* out = g_featT + outOff + (size_t)b * P * 256;
#pragma unroll
  for (int rr = 0; rr < 4; rr++) {
    int pp = tx + 32 * rr;
    int p = p0 + pp;
    if (p < P) {
      float4 v;
      v.x = tile[ty * 4 + 0][pp];
      v.y = tile[ty * 4 + 1][pp];
      v.z = tile[ty * 4 + 2][pp];
      v.w = tile[ty * 4 + 3][pp];
      *(float4*)(out + (size_t)p * 256 + c0 + ty * 4) = v;
    }
  }
}

// scalar transpose for level 3 (P=625, rows not 16B-aligned)
__global__ void transpose_scalar_kernel(const float* __restrict__ in, int P, long long outOff) {
  __shared__ float tile[32][33];
  int b = blockIdx.z;
  int p0 = blockIdx.x * 32, c0 = blockIdx.y * 32;
  int tx = threadIdx.x, ty = threadIdx.y;
#pragma unroll
  for (int rr = 0; rr < 4; rr++) {
    int c = c0 + ty + rr * 8;
    int p = p0 + tx;
    if (p < P) tile[ty + rr * 8][tx] = in[((size_t)b * 256 + c) * P + p];
  }
  __syncthreads();
  float* out = g_featT + outOff + (size_t)b * P * 256;
#pragma unroll
  for (int rr = 0; rr < 4; rr++) {
    int p = p0 + ty + rr * 8;
    int c = c0 + tx;
    if (p < P) out[(size_t)p * 256 + c] = tile[tx][ty + rr * 8];
  }
}

// ---------------------------------------------------------------------------
// exact top-k per (level, image) + fused decode
// ---------------------------------------------------------------------------
__global__ void __launch_bounds__(1024) topk_kernel(InPtrs a) {
  int lvl = blockIdx.x, b = blockIdx.y;
  int G = c_G[lvl];
  int ncell = G * G;
  int n = 3 * ncell;
  int k = c_topk[lvl];
  const float* obj = a.obj[lvl] + (size_t)b * n;

  __shared__ int hist[256];
  __shared__ unsigned sh_prefix;
  __shared__ int sh_kc;
  __shared__ int sh_cnt;
  __shared__ ull keys[1024];

  bool vec = ((n & 3) == 0);
  int nvec = n >> 2;
  int nvec_r = (nvec + 1023) & ~1023;
  int lane = threadIdx.x & 31;

  unsigned prefix = 0;
  int kc = k;
  for (int pass = 0; pass < 4; pass++) {
    int pos = 24 - 8 * pass;
    unsigned himask = (pass == 0) ? 0u : (0xFFFFFFFFu << (pos + 8));
    for (int h = threadIdx.x; h < 256; h += 1024) hist[h] = 0;
    __syncthreads();
    if (vec) {
      const float4* o4 = (const float4*)obj;
      for (int t = threadIdx.x; t < nvec_r; t += 1024) {
        bool inb = (t < nvec);
        float4 v = inb ? o4[t] : make_float4(0.f, 0.f, 0.f, 0.f);
        float vals[4] = {v.x, v.y, v.z, v.w};
#pragma unroll
        for (int e = 0; e < 4; e++) {
          unsigned u = ordkey(vals[e]);
          bool okk = inb && ((u & himask) == prefix);
          unsigned key = okk ? ((u >> pos) & 255u) : 0xFFFFFFFFu;
          unsigned mm = __match_any_sync(0xFFFFFFFFu, key);
          int leader = __ffs(mm) - 1;
          if (okk && lane == leader)
            atomicAdd(&hist[key], __popc(mm));
        }
      }
    } else {
      for (int t = threadIdx.x; t < n; t += 1024) {
        unsigned u = ordkey(obj[t]);
        if ((u & himask) == prefix) atomicAdd(&hist[(u >> pos) & 255], 1);
      }
    }
    __syncthreads();
    if (threadIdx.x == 0) {
      int cum = 0, bin = 255;
      for (; bin >= 0; bin--) {
        int c = hist[bin];
        if (cum + c >= kc) break;
        cum += c;
      }
      sh_prefix = prefix | ((unsigned)bin << pos);
      sh_kc = kc - cum;
    }
    __syncthreads();
    prefix = sh_prefix;
    kc = sh_kc;
    __syncthreads();
  }
  unsigned T = prefix;

  for (int t = threadIdx.x; t < 1024; t += 1024) keys[t] = 0ull;
  if (threadIdx.x == 0) sh_cnt = 0;
  __syncthreads();
  if (vec) {
    const float4* o4 = (const float4*)obj;
    for (int t = threadIdx.x; t < nvec; t += 1024) {
      float4 v = o4[t];
      float vals[4] = {v.x, v.y, v.z, v.w};
#pragma unroll
      for (int e = 0; e < 4; e++) {
        unsigned u = ordkey(vals[e]);
        if (u >= T) {
          int src = t * 4 + e;
          int aa = src / ncell, yx = src - aa * ncell;
          int p = atomicAdd(&sh_cnt, 1);
          if (p < 1024)
            keys[p] = ((ull)u << 32) | (unsigned)(~(yx * 3 + aa));
        }
      }
    }
  } else {
    for (int t = threadIdx.x; t < n; t += 1024) {
      unsigned u = ordkey(obj[t]);
      if (u >= T) {
        int aa = t / ncell, yx = t - aa * ncell;
        int p = atomicAdd(&sh_cnt, 1);
        if (p < 1024)
          keys[p] = ((ull)u << 32) | (unsigned)(~(yx * 3 + aa));
      }
    }
  }
  __syncthreads();
  for (int kk = 2; kk <= 1024; kk <<= 1) {
    for (int j = kk >> 1; j > 0; j >>= 1) {
      for (int t = threadIdx.x; t < 1024; t += 1024) {
        int ixj = t ^ j;
        if (ixj > t) {
          ull A = keys[t], C = keys[ixj];
          bool desc = ((t & kk) == 0);
          if (desc ? (A < C) : (A > C)) { keys[t] = C; keys[ixj] = A; }
        }
      }
      __syncthreads();
    }
  }

  // fused decode
  int slotbase = b * NSEL + c_slotoff[lvl];
  const float* dl = a.dlt[lvl];
  size_t GG = (size_t)G * G;
  float st = (float)c_stride[lvl];
  for (int i = threadIdx.x; i < k; i += 1024) {
    ull K = keys[i];
    unsigned u = (unsigned)(K >> 32);
    int flat = (int)~(unsigned)(K & 0xFFFFFFFFull);
    float logit = inv_ordkey(u);
    int aa = flat % 3;
    int cell = flat / 3;
    int y = cell / G, x = cell - y * G;
    float sx = (float)x * st, sy = (float)y * st;
    float x1a = sx + c_cell[lvl][aa][0];
    float y1a = sy + c_cell[lvl][aa][1];
    float x2a = sx + c_cell[lvl][aa][2];
    float y2a = sy + c_cell[lvl][aa][3];
    float wa = x2a - x1a, ha = y2a - y1a;
    float cxa = x1a + 0.5f * wa, cya = y1a + 0.5f * ha;

    size_t p0 = ((size_t)b * 12 + aa * 4) * GG + (size_t)y * G + x;
    float dx = dl[p0], dy = dl[p0 + GG];
    float dw = fminf(dl[p0 + 2 * GG], BBOX_CLIP);
    float dh = fminf(dl[p0 + 3 * GG], BBOX_CLIP);

    float cx = __fadd_rn(__fmul_rn(dx, wa), cxa);
    float cy = __fadd_rn(__fmul_rn(dy, ha), cya);
    float w  = __fmul_rn(expf(dw), wa);
    float h  = __fmul_rn(expf(dh), ha);
    float hw = __fmul_rn(0.5f, w), hh = __fmul_rn(0.5f, h);
    float x1 = __fsub_rn(cx, hw), y1 = __fsub_rn(cy, hh);
    float x2 = __fadd_rn(cx, hw), y2 = __fadd_rn(cy, hh);
    x1 = fminf(fmaxf(x1, 0.f), 800.f);
    x2 = fminf(fmaxf(x2, 0.f), 800.f);
    y1 = fminf(fmaxf(y1, 0.f), 800.f);
    y2 = fminf(fmaxf(y2, 0.f), 800.f);
    bool valid = (__fsub_rn(x2, x1) >= 0.001f) && (__fsub_rn(y2, y1) >= 0.001f);

    g_boxes[slotbase + i] = make_float4(x1, y1, x2, y2);
    g_key[slotbase + i] = valid ? xla_sigmoid(logit) : -INFINITY;
    float m = fmaxf(fmaxf(x1, y1), fmaxf(x2, y2));
    atomicMax(&g_maxc_bits[b], __float_as_int(m));
  }
}

// ---------------------------------------------------------------------------
// sortA: 4 blocks; block (b, half) fully sorts its 4096 keys
// ---------------------------------------------------------------------------
__global__ void __launch_bounds__(1024) sortA_kernel() {
  __shared__ ull sk[4096];
  int b = blockIdx.x >> 1, half = blockIdx.x & 1;
  int base = half * 4096;
  for (int t = threadIdx.x; t < 4096; t += 1024) {
    int s = base + t;
    unsigned u = (s < NSEL) ? ordkey(g_key[b * NSEL + s]) : KU_NEGINF;
    sk[t] = ((ull)u << 32) | (unsigned)(~s);
  }
  __syncthreads();
  bool wantDesc = (half == 0);
  for (int kk = 2; kk <= 4096; kk <<= 1) {
    for (int j = kk >> 1; j > 0; j >>= 1) {
      for (int t = threadIdx.x; t < 4096; t += 1024) {
        int ixj = t ^ j;
        if (ixj > t) {
          ull A = sk[t], C = sk[ixj];
          bool descPair = (((t & kk) == 0) == wantDesc);
          if (descPair ? (A < C) : (A > C)) { sk[t] = C; sk[ixj] = A; }
        }
      }
      __syncthreads();
    }
  }
  for (int t = threadIdx.x; t < 4096; t += 1024)
    g_sk[b * NPAD + base + t] = sk[t];
}

// ---------------------------------------------------------------------------
// sortB: per-image 13-pass bitonic merge (descending) + tail
// ---------------------------------------------------------------------------
__global__ void __launch_bounds__(1024) sortB_kernel() {
  extern __shared__ ull sk[];
  int b = blockIdx.x;
  for (int t = threadIdx.x; t < NPAD; t += 1024) sk[t] = g_sk[b * NPAD + t];
  __syncthreads();
  for (int j = NPAD >> 1; j > 0; j >>= 1) {
    for (int t = threadIdx.x; t < NPAD; t += 1024) {
      int ixj = t ^ j;
      if (ixj > t) {
        ull A = sk[t], C = sk[ixj];
        if (A < C) { sk[t] = C; sk[ixj] = A; }
      }
    }
    __syncthreads();
  }
  float maxc = __int_as_float(g_maxc_bits[b]);
  float mc1 = __fadd_rn(maxc, 1.0f);
  for (int i = threadIdx.x; i < NSEL; i += 1024) {
    ull K = sk[i];
    unsigned slot = ~(unsigned)(K & 0xFFFFFFFFull);
    unsigned ku = (unsigned)(K >> 32);
    float4 bx = g_boxes[b * NSEL + slot];
    g_sraw[b * NSEL + i] = bx;
    int lvl = (slot < 1000) ? 0 : (slot < 2000) ? 1 : (slot < 3000) ? 2 : (slot < 4000) ? 3 : 4;
    float off = __fmul_rn((float)lvl, mc1);
    g_soff[b * NSEL + i] = make_float4(__fadd_rn(bx.x, off), __fadd_rn(bx.y, off),
                                       __fadd_rn(bx.z, off), __fadd_rn(bx.w, off));
    if (ku != KU_NEGINF)
      atomicOr(&g_live[b][i >> 6], 1ull << (i & 63));
  }
}

// ---------------------------------------------------------------------------
// IoU suppression bitmask. Upper triangle only.
// ---------------------------------------------------------------------------
__global__ void iou_kernel() {
  int cw = blockIdx.x, rb = blockIdx.y, b = blockIdx.z;
  if (cw < rb) return;
  int t = threadIdx.x;
  int i = rb * 64 + t;
  __shared__ float4 cb[64];
  __shared__ float  ca[64];
  int j0 = cw * 64;
  if (j0 + t < NSEL) {
    float4 q = g_soff[b * NSEL + j0 + t];
    cb[t] = q;
    ca[t] = __fmul_rn(__fsub_rn(q.z, q.x), __fsub_rn(q.w, q.y));
  } else {
    cb[t] = make_float4(0.f, 0.f, 0.f, 0.f);
    ca[t] = 0.f;
  }
  __syncthreads();
  if (i >= NSEL) return;
  float4 p = g_soff[b * NSEL + i];
  float pa = __fmul_rn(__fsub_rn(p.z, p.x), __fsub_rn(p.w, p.y));
  ull bits = 0;
#pragma unroll 4
  for (int jj = 0; jj < 64; jj++) {
    int j = j0 + jj;
    if (j > i && j < NSEL) {
      float4 q = cb[jj];
      float ltx = fmaxf(p.x, q.x), lty = fmaxf(p.y, q.y);
      float rbx = fminf(p.z, q.z), rby = fminf(p.w, q.w);
      float w = fmaxf(__fsub_rn(rbx, ltx), 0.f);
      float h = fmaxf(__fsub_rn(rby, lty), 0.f);
      float inter = __fmul_rn(w, h);
      if (inter > 0.f) {
        float denom = __fsub_rn(__fadd_rn(pa, ca[jj]), inter);
        if ((double)inter >= IOU_MID * (double)denom)
          bits |= 1ull << jj;
      }
    }
  }
  g_mask[((size_t)b * NSEL + i) * MWP + cw] = bits;
}

// ---------------------------------------------------------------------------
// sequential NMS scan: per-index loop, 32-deep ring, prefetch i+32,
// wait_group 31. Warp-uniform cur word. Fused lvl assignment.
// ---------------------------------------------------------------------------
__device__ __forceinline__ void cpasync16(void* sm, const void* gm) {
  unsigned sa = (unsigned)__cvta_generic_to_shared(sm);
  asm volatile("cp.async.ca.shared.global [%0], [%1], 16;" :: "r"(sa), "l"(gm));
}

__global__ void nms_scan_kernel(float* __restrict__ fin) {
  int b = blockIdx.x;
  int lane = threadIdx.x;
  __shared__ __align__(16) ull ring[32][MWP];
  __shared__ int keep_s[1000];

  int w0 = lane, w1 = 32 + lane, w2 = 64 + lane;  // w2 merge valid for lane<8
  ull live0 = g_live[b][w0];
  ull live1 = g_live[b][w1];
  ull live2 = (w2 < MW) ? g_live[b][w2] : 0ull;
  ull remv0 = 0, remv1 = 0, remv2 = 0;

  const ull* mbase = g_mask + (size_t)b * NSEL * MWP;
  for (int d = 0; d < 32; d++) {
    const ull* mrow = mbase + (size_t)d * MWP;
    ull* dst = ring[d];
    cpasync16(&dst[lane * 2], mrow + lane * 2);
    if (lane < 4) cpasync16(&dst[64 + lane * 2], mrow + 64 + lane * 2);
    asm volatile("cp.async.commit_group;");
  }

  ull cur = 0;
  int cnt = 0;
  for (int i = 0; i < NSEL; i++) {
    asm volatile("cp.async.wait_group 31;");
    int iw = i >> 6, ib = i & 63;
    if (ib == 0) {
      int s = iw >> 5;
      ull lv = (s == 0) ? live0 : ((s == 1) ? live1 : live2);
      ull rv = (s == 0) ? remv0 : ((s == 1) ? remv1 : remv2);
      cur = __shfl_sync(0xFFFFFFFFu, lv & ~rv, iw & 31);
    }
    if ((cur >> ib) & 1ull) {
      int slot = i & 31;
      remv0 |= ring[slot][w0];
      remv1 |= ring[slot][w1];
      if (lane < 8) remv2 |= ring[slot][w2];
      cur &= ~ring[slot][iw];
      if (lane == 0) keep_s[cnt] = i;
      cnt++;
      if (cnt >= 1000) break;
    }
    int pf = i + 32;
    if (pf < NSEL) {
      int slot = pf & 31;
      const ull* mrow = mbase + (size_t)pf * MWP;
      ull* dst = ring[slot];
      cpasync16(&dst[lane * 2], mrow + lane * 2);
      if (lane < 4) cpasync16(&dst[64 + lane * 2], mrow + 64 + lane * 2);
    }
    asm volatile("cp.async.commit_group;");
  }
  asm volatile("cp.async.wait_all;");
  __syncwarp();
  float4* fo = (float4*)fin;
  for (int j = lane; j < 1000; j += 32) {
    float4 v = make_float4(0.f, 0.f, 0.f, 0.f);
    if (j < cnt) v = g_sraw[b * NSEL + keep_s[j]];
    fo[b * 1000 + j] = v;
    float area = __fmul_rn(__fsub_rn(v.z, v.x), __fsub_rn(v.w, v.y));
    float arg = __fadd_rn(__fdiv_rn(sqrtf(area), 224.0f), 1e-6f);
    float l = floorf(__fadd_rn(4.0f, log2f(arg)));
    l = fminf(fmaxf(l, 2.0f), 5.0f);
    g_lvl[b * 1000 + j] = (int)l - 2;
  }
}

// ---------------------------------------------------------------------------
// roi align: 2 blocks per roi (25 + 24 pixels), 256 channel threads.
// smem 25*257*4 = 25.7KB -> 8 blocks/SM.
// ---------------------------------------------------------------------------
__global__ void __launch_bounds__(256) roialign_kernel(const float* __restrict__ fin,
                                                       float* __restrict__ out) {
  extern __shared__ float outs[];  // [npix][257]
  __shared__ float lx[14], hx[14], ly[14], hy[14], vxf[14], vyf[14];
  __shared__ int xl[14], xh[14], yl[14], yh[14];

  int r = blockIdx.x >> 1;
  int half = blockIdx.x & 1;
  int pbase = half ? 25 : 0;
  int npix  = half ? 24 : 25;
  int c = threadIdx.x;
  int li = g_lvl[r];
  float4 roi = ((const float4*)fin)[r];
  int W = c_featW[li];
  float sc = c_featScale[li];
  int b = r / 1000;

  if (c < 14) {
    float x1 = __fmul_rn(roi.x, sc), x2 = __fmul_rn(roi.z, sc);
    float bw = __fdiv_rn(fmaxf(__fsub_rn(x2, x1), 1.0f), 7.0f);
    float gg = ((float)c + 0.5f) / 2.0f;
    float xs = __fadd_rn(x1, __fmul_rn(bw, gg));
    vxf[c] = (xs >= -1.0f && xs <= (float)W) ? 1.0f : 0.0f;
    float xc = fminf(fmaxf(xs, 0.0f), (float)(W - 1));
    int xlo = (int)floorf(xc);
    xl[c] = xlo;
    xh[c] = min(xlo + 1, W - 1);
    float l = __fsub_rn(xc, (float)xlo);
    lx[c] = l;
    hx[c] = 1.0f - l;
  }
  if (c >= 16 && c < 30) {
    int q = c - 16;
    float y1 = __fmul_rn(roi.y, sc), y2 = __fmul_rn(roi.w, sc);
    float bh = __fdiv_rn(fmaxf(__fsub_rn(y2, y1), 1.0f), 7.0f);
    float gg = ((float)q + 0.5f) / 2.0f;
    float ys = __fadd_rn(y1, __fmul_rn(bh, gg));
    vyf[q] = (ys >= -1.0f && ys <= (float)W) ? 1.0f : 0.0f;
    float yc = fminf(fmaxf(ys, 0.0f), (float)(W - 1));
    int ylo = (int)floorf(yc);
    yl[q] = ylo;
    yh[q] = min(ylo + 1, W - 1);
    float l = __fsub_rn(yc, (float)ylo);
    ly[q] = l;
    hy[q] = 1.0f - l;
  }
  __syncthreads();

  const float* F = g_featT + c_featOff[li] + (size_t)b * W * W * 256 + c;
#pragma unroll 1
  for (int pl = 0; pl < npix; pl++) {
    int p = pbase + pl;
    int py = p / 7, px = p - py * 7;
    float acc = 0.f;
#pragma unroll
    for (int sy = 0; sy < 2; sy++) {
#pragma unroll
      for (int sxi = 0; sxi < 2; sxi++) {
        int ii = py * 2 + sy, jj = px * 2 + sxi;
        int y0 = yl[ii], y1 = yh[ii], x0 = xl[jj], x1 = xh[jj];
        const float* r0 = F + (size_t)(y0 * W) * 256;
        const float* r1 = F + (size_t)(y1 * W) * 256;
        float v00 = r0[(size_t)x0 * 256];
        float v01 = r0[(size_t)x1 * 256];
        float v10 = r1[(size_t)x0 * 256];
        float v11 = r1[(size_t)x1 * 256];
        float t = (hy[ii] * hx[jj]) * v00 + (hy[ii] * lx[jj]) * v01 +
                  (ly[ii] * hx[jj]) * v10 + (ly[ii] * lx[jj]) * v11;
        acc += t * (vyf[ii] * vxf[jj]);
      }
    }
    outs[pl * 257 + c] = acc * 0.25f;
  }
  __syncthreads();
  float* o = out + (size_t)r * 12544;
  int tot = npix * 256;
  for (int g = c; g < tot; g += 256) {
    int cc = g / npix, pl = g - cc * npix;
    o[cc * 49 + pbase + pl] = outs[pl * 257 + cc];
  }
}

// ---------------------------------------------------------------------------
// launch: transposes forked onto a side stream, joined before roialign
// ---------------------------------------------------------------------------
extern "C" void kernel_launch(void* const* d_in, const int* in_sizes, int n_in,
                              void* d_out, int out_size) {
  (void)n_in; (void)out_size;
  static cudaStream_t s_side = 0;
  static cudaEvent_t  s_fork = 0, s_join = 0;
  if (!s_side) {
    cudaStreamCreateWithFlags(&s_side, cudaStreamNonBlocking);
    cudaEventCreateWithFlags(&s_fork, cudaEventDisableTiming);
    cudaEventCreateWithFlags(&s_join, cudaEventDisableTiming);
  }

  InPtrs a;
  bool interleaved = (in_sizes[2] == 4 * in_sizes[1]);
  for (int i = 0; i < 5; i++) {
    if (interleaved) {
      a.obj[i] = (const float*)d_in[1 + 2 * i];
      a.dlt[i] = (const float*)d_in[2 + 2 * i];
    } else {
      a.obj[i] = (const float*)d_in[1 + i];
      a.dlt[i] = (const float*)d_in[6 + i];
    }
  }
  const float* feats[4] = {(const float*)d_in[11], (const float*)d_in[12],
                           (const float*)d_in[13], (const float*)d_in[14]};
  float* fin = (float*)d_out;
  float* bf  = (float*)d_out + 8000;

  cudaFuncSetAttribute(sortB_kernel, cudaFuncAttributeMaxDynamicSharedMemorySize, 65536);

  init_kernel<<<1, 256>>>();

  // fork: transposes on side stream
  cudaEventRecord(s_fork, 0);
  cudaStreamWaitEvent(s_side, s_fork, 0);
  const int Ps[4] = {40000, 10000, 2500, 625};
  const long long offs[4] = {0, 20480000, 25600000, 26880000};
  for (int l = 0; l < 3; l++) {
    dim3 grid((Ps[l] + 127) / 128, 8, 2);
    transpose_vec_kernel<<<grid, 256, 0, s_side>>>(feats[l], Ps[l], offs[l]);
  }
  {
    dim3 grid((Ps[3] + 31) / 32, 8, 2);
    transpose_scalar_kernel<<<grid, dim3(32, 8), 0, s_side>>>(feats[3], Ps[3], offs[3]);
  }
  cudaEventRecord(s_join, s_side);

  // main chain on default stream
  topk_kernel<<<dim3(5, 2), 1024>>>(a);
  sortA_kernel<<<4, 1024>>>();
  sortB_kernel<<<2, 1024, 65536>>>();
  iou_kernel<<<dim3(MW, MW, 2), 64>>>();
  nms_scan_kernel<<<2, 32>>>(fin);

  // join before roialign (needs g_featT)
  cudaStreamWaitEvent(0, s_join, 0);
  roialign_kernel<<<4000, 256, 25700>>>(fin, bf);
}